// round 5
// baseline (speedup 1.0000x reference)
#include <cuda_runtime.h>
#include <cuda_bf16.h>
#include <cstdint>

#define BATCH 16
#define HH 256
#define WW 256
#define NPIX (BATCH*HH*WW)

// ---- scratch (__device__ globals; no allocs allowed) ----
__device__ float g_xnew[(size_t)NPIX * 16];   // 64MB
__device__ float g_aold[NPIX];                // 4MB
__device__ float g_anew[NPIX];                // 4MB

// ================= warp-MMA helpers =================
__device__ __forceinline__ uint32_t smem_u32(const void* p) {
    uint32_t a;
    asm("{ .reg .u64 t; cvta.to.shared.u64 t, %1; cvt.u32.u64 %0, t; }" : "=r"(a) : "l"(p));
    return a;
}
__device__ __forceinline__ void ldsm4(uint32_t* r, uint32_t addr) {
    asm volatile("ldmatrix.sync.aligned.m8n8.x4.shared.b16 {%0,%1,%2,%3}, [%4];"
        : "=r"(r[0]), "=r"(r[1]), "=r"(r[2]), "=r"(r[3]) : "r"(addr));
}
__device__ __forceinline__ void mma_bf16(float* d, const uint32_t* a, uint32_t b0, uint32_t b1) {
    asm volatile("mma.sync.aligned.m16n8k16.row.col.f32.bf16.bf16.f32 "
        "{%0,%1,%2,%3}, {%4,%5,%6,%7}, {%8,%9}, {%0,%1,%2,%3};"
        : "+f"(d[0]), "+f"(d[1]), "+f"(d[2]), "+f"(d[3])
        : "r"(a[0]), "r"(a[1]), "r"(a[2]), "r"(a[3]), "r"(b0), "r"(b1));
}
__device__ __forceinline__ uint16_t bf16_bits(float f) {
    return __bfloat16_as_ushort(__float2bfloat16(f));
}
__device__ __forceinline__ float bf16_val(uint16_t u) {
    return __bfloat162float(__ushort_as_bfloat16(u));
}
__device__ __forceinline__ uint32_t pack2(float a, float b) {
    return (uint32_t)bf16_bits(a) | ((uint32_t)bf16_bits(b) << 16);
}

// ================= Pass 1 ===================================================
// CTA = 128 pixels (half row), 256 threads / 8 warps. Warp w owns pixels
// [16w, 16w+16). All 3 split-bf16 terms via register reuse:
//   term1 = Ahi*Bhi, term2 = Alo*Bhi, term3 = Ahi*Blo.
//
// SMEM (bytes):
//   A1  @ 0      : bf16 [128 px][104]  (k: hi 0:48 | lo 48:96)  = 26624
//   B1  @ 26624  : bf16 [128 n][104]   (k: W1hi 0:48 | W1lo 48:96) = 26624
//   B2  @ 53248  : bf16 [16 n][264]    (k: W2hi 0:128 | W2lo 128:256) = 8448
//   XH  @ 61696  : f32  [48][132]      = 25344
//   b1v @ 87040  : f32[128] = 512
//   b2v @ 87552  : f32[16]  = 64
#define SM_A1   0
#define SM_B1   26624
#define SM_B2   53248
#define SM_XH   61696
#define SM_B1V  87040
#define SM_B2V  87552
#define SMEM_BYTES 87616

extern __shared__ unsigned char sm[];

__global__ void __launch_bounds__(256, 2) nca_pass1(
    const float* __restrict__ x,  const float* __restrict__ W1,
    const float* __restrict__ b1, const float* __restrict__ W2,
    const float* __restrict__ b2, const float* __restrict__ ru)
{
    const uint32_t smb = smem_u32(sm);
    float* XH = (float*)(sm + SM_XH);
    __nv_bfloat16* A1 = (__nv_bfloat16*)(sm + SM_A1);
    __nv_bfloat16* B1 = (__nv_bfloat16*)(sm + SM_B1);
    __nv_bfloat16* B2 = (__nv_bfloat16*)(sm + SM_B2);

    const int t    = threadIdx.x;
    const int w    = t >> 5;
    const int lane = t & 31;
    const int bid  = blockIdx.x;
    const int tile = bid & 1;
    const int row  = bid >> 1;
    const int b    = row >> 8;
    const int i    = row & 255;
    const int j0   = tile << 7;

    // ---- phase A: build weight tiles from global W1/W2 (bf16 hi/lo) ----
    for (int q4 = t; q4 < 1536; q4 += 256) {       // W1 [48k][128n]
        int k = q4 >> 5;
        int n = (q4 & 31) << 2;
        float4 v = ((const float4*)W1)[q4];
        float vv[4] = {v.x, v.y, v.z, v.w};
        #pragma unroll
        for (int e = 0; e < 4; e++) {
            __nv_bfloat16 h = __float2bfloat16(vv[e]);
            B1[(n + e) * 104 + k]      = h;
            B1[(n + e) * 104 + 48 + k] = __float2bfloat16(vv[e] - __bfloat162float(h));
        }
    }
    for (int q4 = t; q4 < 512; q4 += 256) {        // W2 [128d][16c]
        int d = q4 >> 2;
        int c = (q4 & 3) << 2;
        float4 v = ((const float4*)W2)[q4];
        float vv[4] = {v.x, v.y, v.z, v.w};
        #pragma unroll
        for (int e = 0; e < 4; e++) {
            __nv_bfloat16 h = __float2bfloat16(vv[e]);
            B2[(c + e) * 264 + d]       = h;
            B2[(c + e) * 264 + 128 + d] = __float2bfloat16(vv[e] - __bfloat162float(h));
        }
    }
    if (t < 128) ((float*)(sm + SM_B1V))[t] = b1[t];
    if (t < 16)  ((float*)(sm + SM_B2V))[t] = b2[t];

    // ---- x-halo: 3 rows x 130 cols x 16 ch -> channel-major XH[48][132] ----
    for (int task = t; task < 1560; task += 256) {
        int rr  = task / 520;
        int rem = task - rr * 520;
        int cc  = rem >> 2;
        int cg  = rem & 3;
        int gi  = i + rr - 1;
        int jc  = j0 + cc - 1;
        float4 v = make_float4(0.f, 0.f, 0.f, 0.f);
        if (gi >= 0 && gi < HH && jc >= 0 && jc < WW)
            v = *(const float4*)(x + (((size_t)(b * HH + gi) * WW + jc) << 4) + (cg << 2));
        float* dst = XH + (rr * 16 + (cg << 2)) * 132 + cc;
        dst[0] = v.x; dst[132] = v.y; dst[264] = v.z; dst[396] = v.w;
    }
    __syncthreads();

    // ---- perceive -> A1 bf16 [128px][hi 0:48 | lo 48:96] ----
    for (int task = t; task < 2048; task += 256) {
        int pp = task & 127;
        int c  = task >> 7;
        const float* r0 = XH + (c)      * 132 + pp;
        const float* r1 = XH + (16 + c) * 132 + pp;
        const float* r2 = XH + (32 + c) * 132 + pp;
        float a00 = r0[0], a01 = r0[1], a02 = r0[2];
        float a10 = r1[0], a11 = r1[1], a12 = r1[2];
        float a20 = r2[0], a21 = r2[1], a22 = r2[2];
        float yv[3];
        yv[0] = a11;
        yv[1] = ((a02 + 2.f * a12 + a22) - (a00 + 2.f * a10 + a20)) * 0.125f;
        yv[2] = ((a20 + 2.f * a21 + a22) - (a00 + 2.f * a01 + a02)) * 0.125f;
        #pragma unroll
        for (int e = 0; e < 3; e++) {
            int k = 3 * c + e;
            __nv_bfloat16 h = __float2bfloat16(yv[e]);
            A1[pp * 104 + k]      = h;
            A1[pp * 104 + 48 + k] = __float2bfloat16(yv[e] - __bfloat162float(h));
        }
    }
    __syncthreads();

    // ---- GEMM1: acc[16 n8-tiles][4] = A1[16w..][96] x B1 (3 terms) ----
    float acc[16][4];
    #pragma unroll
    for (int j = 0; j < 16; j++)
        #pragma unroll
        for (int r = 0; r < 4; r++) acc[j][r] = 0.f;

    uint32_t ah[3][4], al[3][4];
    {
        const uint32_t aBase = smb + SM_A1 + (16 * w + (lane & 15)) * 208 + (lane >> 4) * 16;
        #pragma unroll
        for (int ks = 0; ks < 3; ks++) {
            ldsm4(ah[ks], aBase + ks * 32);
            ldsm4(al[ks], aBase + 96 + ks * 32);
        }
        const uint32_t bBase = smb + SM_B1 + ((lane & 7) + ((lane >> 4) & 1) * 8) * 208
                                           + ((lane >> 3) & 1) * 16;
        #pragma unroll
        for (int jj = 0; jj < 8; jj++) {
            #pragma unroll
            for (int ks = 0; ks < 3; ks++) {
                uint32_t bh[4], bl[4];
                ldsm4(bh, bBase + jj * (16 * 208) + ks * 32);
                ldsm4(bl, bBase + jj * (16 * 208) + 96 + ks * 32);
                mma_bf16(acc[2 * jj],     ah[ks], bh[0], bh[1]);
                mma_bf16(acc[2 * jj + 1], ah[ks], bh[2], bh[3]);
                mma_bf16(acc[2 * jj],     al[ks], bh[0], bh[1]);
                mma_bf16(acc[2 * jj + 1], al[ks], bh[2], bh[3]);
                mma_bf16(acc[2 * jj],     ah[ks], bl[0], bl[1]);
                mma_bf16(acc[2 * jj + 1], ah[ks], bl[2], bl[3]);
            }
        }
    }

    // ---- GEMM2 (register-fed): C-frag of GEMM1 == A-frag of GEMM2 ----
    // h = relu(acc + b1) split hi/lo in registers; dx = Hhi*W2hi + Hlo*W2hi + Hhi*W2lo
    float acc2[2][4];
    #pragma unroll
    for (int j = 0; j < 2; j++)
        #pragma unroll
        for (int r = 0; r < 4; r++) acc2[j][r] = 0.f;

    const int c0 = (lane & 3) * 2;
    {
        const float* b1s = (const float*)(sm + SM_B1V);
        const uint32_t b2Base = smb + SM_B2 + ((lane & 7) + ((lane >> 4) & 1) * 8) * 528
                                            + ((lane >> 3) & 1) * 16;
        #pragma unroll
        for (int ks = 0; ks < 8; ks++) {
            int n0 = 16 * ks + c0;
            int n1 = n0 + 8;
            float bn00 = b1s[n0], bn01 = b1s[n0 + 1];
            float bn10 = b1s[n1], bn11 = b1s[n1 + 1];
            float v00 = fmaxf(acc[2 * ks][0] + bn00, 0.f);
            float v01 = fmaxf(acc[2 * ks][1] + bn01, 0.f);
            float v02 = fmaxf(acc[2 * ks][2] + bn00, 0.f);
            float v03 = fmaxf(acc[2 * ks][3] + bn01, 0.f);
            float v10 = fmaxf(acc[2 * ks + 1][0] + bn10, 0.f);
            float v11 = fmaxf(acc[2 * ks + 1][1] + bn11, 0.f);
            float v12 = fmaxf(acc[2 * ks + 1][2] + bn10, 0.f);
            float v13 = fmaxf(acc[2 * ks + 1][3] + bn11, 0.f);
            uint32_t ahi[4], alo[4];
            ahi[0] = pack2(v00, v01);
            ahi[1] = pack2(v02, v03);
            ahi[2] = pack2(v10, v11);
            ahi[3] = pack2(v12, v13);
            alo[0] = pack2(v00 - bf16_val((uint16_t)ahi[0]), v01 - bf16_val((uint16_t)(ahi[0] >> 16)));
            alo[1] = pack2(v02 - bf16_val((uint16_t)ahi[1]), v03 - bf16_val((uint16_t)(ahi[1] >> 16)));
            alo[2] = pack2(v10 - bf16_val((uint16_t)ahi[2]), v11 - bf16_val((uint16_t)(ahi[2] >> 16)));
            alo[3] = pack2(v12 - bf16_val((uint16_t)ahi[3]), v13 - bf16_val((uint16_t)(ahi[3] >> 16)));

            uint32_t bh[4], bl[4];
            ldsm4(bh, b2Base + ks * 32);
            ldsm4(bl, b2Base + 256 + ks * 32);   // W2lo starts at k=128 -> byte 256 (BUG FIX: was +512)
            mma_bf16(acc2[0], ahi, bh[0], bh[1]);
            mma_bf16(acc2[1], ahi, bh[2], bh[3]);
            mma_bf16(acc2[0], alo, bh[0], bh[1]);
            mma_bf16(acc2[1], alo, bh[2], bh[3]);
            mma_bf16(acc2[0], ahi, bl[0], bl[1]);
            mma_bf16(acc2[1], ahi, bl[2], bl[3]);
        }
    }

    // ---- epilogue: dx + stochastic update -> g_xnew / alpha arrays ----
    {
        const float* b2s = (const float*)(sm + SM_B2V);
        const int p0 = 16 * w + (lane >> 2);
        float bc0 = b2s[c0], bc1 = b2s[c0 + 1], bc8 = b2s[c0 + 8], bc9 = b2s[c0 + 9];
        #pragma unroll
        for (int px = 0; px < 2; px++) {
            int p = p0 + px * 8;
            float xo0 = XH[(16 + c0)     * 132 + 1 + p];
            float xo1 = XH[(16 + c0 + 1) * 132 + 1 + p];
            float xo2 = XH[(16 + c0 + 8) * 132 + 1 + p];
            float xo3 = XH[(16 + c0 + 9) * 132 + 1 + p];
            size_t pix = (size_t)(b * HH + i) * WW + j0 + p;
            float um = (ru[pix] <= 0.5f) ? 1.f : 0.f;
            float xn0 = xo0 + (acc2[0][2 * px]     + bc0) * um;
            float xn1 = xo1 + (acc2[0][2 * px + 1] + bc1) * um;
            float xn2 = xo2 + (acc2[1][2 * px]     + bc8) * um;
            float xn3 = xo3 + (acc2[1][2 * px + 1] + bc9) * um;
            *(float2*)(g_xnew + pix * 16 + c0)     = make_float2(xn0, xn1);
            *(float2*)(g_xnew + pix * 16 + c0 + 8) = make_float2(xn2, xn3);
            if ((lane & 3) == 1) {                 // c0==2 -> channel 3 = slot 1
                g_aold[pix] = xo1;
                g_anew[pix] = xn1;
            }
        }
    }
}

// ================= Pass 2 ===================================================
__global__ void __launch_bounds__(256) nca_pass2(float* __restrict__ out)
{
    __shared__ float sao[3][256];
    __shared__ float san[3][256];
    const int t   = threadIdx.x;
    const int row = blockIdx.x;
    const int b   = row >> 8;
    const int i   = row & 255;

    // issue x loads early (independent of mask math)
    size_t pix = (size_t)row * WW + t;
    float4 v0 = ((const float4*)(g_xnew + pix * 16))[0];
    float4 v1 = ((const float4*)(g_xnew + pix * 16))[1];
    float4 v2 = ((const float4*)(g_xnew + pix * 16))[2];
    float4 v3 = ((const float4*)(g_xnew + pix * 16))[3];

    #pragma unroll
    for (int rr = 0; rr < 3; rr++) {
        int gi = i + rr - 1;
        float vo = -1e30f, vn = -1e30f;
        if (gi >= 0 && gi < HH) {
            size_t idx = (size_t)(b * HH + gi) * WW + t;
            vo = g_aold[idx];
            vn = g_anew[idx];
        }
        sao[rr][t] = vo;
        san[rr][t] = vn;
    }
    __syncthreads();

    float mo = -1e30f, mn = -1e30f;
    #pragma unroll
    for (int rr = 0; rr < 3; rr++) {
        #pragma unroll
        for (int dc = 0; dc < 3; dc++) {
            int jc = t + dc - 1;
            if (jc >= 0 && jc < WW) {
                mo = fmaxf(mo, sao[rr][jc]);
                mn = fmaxf(mn, san[rr][jc]);
            }
        }
    }
    float mask = (mo > 0.1f && mn > 0.1f) ? 1.f : 0.f;

    float4* dst = (float4*)(out + pix * 16);
    v0.x *= mask; v0.y *= mask; v0.z *= mask; v0.w *= mask;
    v1.x *= mask; v1.y *= mask; v1.z *= mask; v1.w *= mask;
    v2.x *= mask; v2.y *= mask; v2.z *= mask; v2.w *= mask;
    v3.x *= mask; v3.y *= mask; v3.z *= mask; v3.w *= mask;
    dst[0] = v0; dst[1] = v1; dst[2] = v2; dst[3] = v3;
}

extern "C" void kernel_launch(void* const* d_in, const int* in_sizes, int n_in,
                              void* d_out, int out_size)
{
    const float *x = nullptr, *W1 = nullptr, *b1 = nullptr,
                *W2 = nullptr, *b2 = nullptr, *ru = nullptr;
    for (int k = 0; k < n_in; k++) {
        switch (in_sizes[k]) {
            case 16777216: x  = (const float*)d_in[k]; break;
            case 6144:     W1 = (const float*)d_in[k]; break;
            case 128:      b1 = (const float*)d_in[k]; break;
            case 2048:     W2 = (const float*)d_in[k]; break;
            case 16:       b2 = (const float*)d_in[k]; break;
            case 1048576:  ru = (const float*)d_in[k]; break;
            default: break;
        }
    }
    float* out = (float*)d_out;

    cudaFuncSetAttribute(nca_pass1, cudaFuncAttributeMaxDynamicSharedMemorySize, SMEM_BYTES);
    nca_pass1<<<8192, 256, SMEM_BYTES>>>(x, W1, b1, W2, b2, ru);
    nca_pass2<<<4096, 256>>>(out);
}

// round 6
// speedup vs baseline: 1.4331x; 1.4331x over previous
#include <cuda_runtime.h>
#include <cuda_bf16.h>
#include <cstdint>

#define BATCH 16
#define HH 256
#define WW 256
#define NPIX (BATCH*HH*WW)

// ---- scratch (__device__ globals; no allocs allowed) ----
__device__ float g_xnew[(size_t)NPIX * 16];   // 64MB
__device__ float g_aold[NPIX];                // 4MB
__device__ float g_anew[NPIX];                // 4MB
__device__ __align__(16) unsigned char g_B1[128 * 104 * 2];  // bf16 [128n][104k] (96 used: hi|lo)
__device__ __align__(16) unsigned char g_B2[16 * 264 * 2];   // bf16 [16n][264k] (256 used: hi|lo)

// ================= warp-MMA helpers =================
__device__ __forceinline__ uint32_t smem_u32(const void* p) {
    uint32_t a;
    asm("{ .reg .u64 t; cvta.to.shared.u64 t, %1; cvt.u32.u64 %0, t; }" : "=r"(a) : "l"(p));
    return a;
}
__device__ __forceinline__ void ldsm4(uint32_t* r, uint32_t addr) {
    asm volatile("ldmatrix.sync.aligned.m8n8.x4.shared.b16 {%0,%1,%2,%3}, [%4];"
        : "=r"(r[0]), "=r"(r[1]), "=r"(r[2]), "=r"(r[3]) : "r"(addr));
}
__device__ __forceinline__ void mma_bf16(float* d, const uint32_t* a, uint32_t b0, uint32_t b1) {
    asm volatile("mma.sync.aligned.m16n8k16.row.col.f32.bf16.bf16.f32 "
        "{%0,%1,%2,%3}, {%4,%5,%6,%7}, {%8,%9}, {%0,%1,%2,%3};"
        : "+f"(d[0]), "+f"(d[1]), "+f"(d[2]), "+f"(d[3])
        : "r"(a[0]), "r"(a[1]), "r"(a[2]), "r"(a[3]), "r"(b0), "r"(b1));
}
__device__ __forceinline__ uint16_t bf16_bits(float f) {
    return __bfloat16_as_ushort(__float2bfloat16(f));
}
__device__ __forceinline__ float bf16_val(uint16_t u) {
    return __bfloat162float(__ushort_as_bfloat16(u));
}
__device__ __forceinline__ uint32_t pack2(float a, float b) {
    return (uint32_t)bf16_bits(a) | ((uint32_t)bf16_bits(b) << 16);
}

// ================= prep: build bf16 hi/lo weight tile images (multi-CTA) ====
__global__ void nca_prep(const float* __restrict__ W1, const float* __restrict__ W2)
{
    int q = blockIdx.x * 256 + threadIdx.x;    // grid 24 x 256 = 6144 threads
    __nv_bfloat16* B1 = (__nv_bfloat16*)g_B1;
    __nv_bfloat16* B2 = (__nv_bfloat16*)g_B2;
    if (q < 6144) {                            // W1 [48k][128n]
        int k = q >> 7, n = q & 127;
        float v = W1[q];
        __nv_bfloat16 h = __float2bfloat16(v);
        B1[n * 104 + k]      = h;
        B1[n * 104 + 48 + k] = __float2bfloat16(v - __bfloat162float(h));
    }
    if (q < 2048) {                            // W2 [128d][16c]
        int d = q >> 4, c = q & 15;
        float v = W2[q];
        __nv_bfloat16 h = __float2bfloat16(v);
        B2[c * 264 + d]       = h;
        B2[c * 264 + 128 + d] = __float2bfloat16(v - __bfloat162float(h));
    }
}

// ================= Pass 1 ===================================================
// CTA = 128 pixels (half row), 256 threads / 8 warps. Warp w owns pixels
// [16w, 16w+16). Split-bf16 3 terms: Ahi*Bhi + Alo*Bhi + Ahi*Blo.
//
// SMEM (bytes):
//   A1  @ 0      : bf16 [128 px][104]  (k: hi 0:48 | lo 48:96)  = 26624
//   B1  @ 26624  : bf16 [128 n][104]   = 26624
//   B2  @ 53248  : bf16 [16 n][264]    (k: W2hi 0:128 | W2lo 128:256) = 8448
//   XH  @ 61696  : f32  [48][132]      = 25344
//   b1v @ 87040  : f32[128] = 512
//   b2v @ 87552  : f32[16]  = 64
#define SM_A1   0
#define SM_B1   26624
#define SM_B2   53248
#define SM_XH   61696
#define SM_B1V  87040
#define SM_B2V  87552
#define SMEM_BYTES 87616

extern __shared__ unsigned char sm[];

__global__ void __launch_bounds__(256, 2) nca_pass1(
    const float* __restrict__ x,  const float* __restrict__ b1,
    const float* __restrict__ b2, const float* __restrict__ ru)
{
    const uint32_t smb = smem_u32(sm);
    float* XH = (float*)(sm + SM_XH);
    __nv_bfloat16* A1 = (__nv_bfloat16*)(sm + SM_A1);

    const int t    = threadIdx.x;
    const int w    = t >> 5;
    const int lane = t & 31;
    const int bid  = blockIdx.x;
    const int tile = bid & 1;
    const int row  = bid >> 1;
    const int b    = row >> 8;
    const int i    = row & 255;
    const int j0   = tile << 7;

    // ---- cooperative tile copies (L2-hot) + bias loads ----
    for (int q = t; q < 1664; q += 256)
        ((float4*)(sm + SM_B1))[q] = ((const float4*)g_B1)[q];
    for (int q = t; q < 528; q += 256)
        ((float4*)(sm + SM_B2))[q] = ((const float4*)g_B2)[q];
    if (t < 128) ((float*)(sm + SM_B1V))[t] = b1[t];
    if (t < 16)  ((float*)(sm + SM_B2V))[t] = b2[t];

    // ---- x-halo: 3 rows x 130 cols x 16 ch -> channel-major XH[48][132] ----
    for (int task = t; task < 1560; task += 256) {
        int rr  = task / 520;
        int rem = task - rr * 520;
        int cc  = rem >> 2;
        int cg  = rem & 3;
        int gi  = i + rr - 1;
        int jc  = j0 + cc - 1;
        float4 v = make_float4(0.f, 0.f, 0.f, 0.f);
        if (gi >= 0 && gi < HH && jc >= 0 && jc < WW)
            v = *(const float4*)(x + (((size_t)(b * HH + gi) * WW + jc) << 4) + (cg << 2));
        float* dst = XH + (rr * 16 + (cg << 2)) * 132 + cc;
        dst[0] = v.x; dst[132] = v.y; dst[264] = v.z; dst[396] = v.w;
    }
    __syncthreads();

    // ---- perceive -> A1 bf16 [128px][hi 0:48 | lo 48:96] ----
    for (int task = t; task < 2048; task += 256) {
        int pp = task & 127;
        int c  = task >> 7;
        const float* r0 = XH + (c)      * 132 + pp;
        const float* r1 = XH + (16 + c) * 132 + pp;
        const float* r2 = XH + (32 + c) * 132 + pp;
        float a00 = r0[0], a01 = r0[1], a02 = r0[2];
        float a10 = r1[0], a11 = r1[1], a12 = r1[2];
        float a20 = r2[0], a21 = r2[1], a22 = r2[2];
        float yv[3];
        yv[0] = a11;
        yv[1] = ((a02 + 2.f * a12 + a22) - (a00 + 2.f * a10 + a20)) * 0.125f;
        yv[2] = ((a20 + 2.f * a21 + a22) - (a00 + 2.f * a01 + a02)) * 0.125f;
        #pragma unroll
        for (int e = 0; e < 3; e++) {
            int k = 3 * c + e;
            __nv_bfloat16 h = __float2bfloat16(yv[e]);
            A1[pp * 104 + k]      = h;
            A1[pp * 104 + 48 + k] = __float2bfloat16(yv[e] - __bfloat162float(h));
        }
    }
    __syncthreads();

    // ---- GEMM1: acc[16 n8-tiles][4] = A1[16w..][96] x B1 (3 terms) ----
    float acc[16][4];
    #pragma unroll
    for (int j = 0; j < 16; j++)
        #pragma unroll
        for (int r = 0; r < 4; r++) acc[j][r] = 0.f;

    uint32_t ah[3][4], al[3][4];
    {
        const uint32_t aBase = smb + SM_A1 + (16 * w + (lane & 15)) * 208 + (lane >> 4) * 16;
        #pragma unroll
        for (int ks = 0; ks < 3; ks++) {
            ldsm4(ah[ks], aBase + ks * 32);
            ldsm4(al[ks], aBase + 96 + ks * 32);
        }
        const uint32_t bBase = smb + SM_B1 + ((lane & 7) + ((lane >> 4) & 1) * 8) * 208
                                           + ((lane >> 3) & 1) * 16;
        #pragma unroll
        for (int jj = 0; jj < 8; jj++) {
            #pragma unroll
            for (int ks = 0; ks < 3; ks++) {
                uint32_t bh[4], bl[4];
                ldsm4(bh, bBase + jj * (16 * 208) + ks * 32);
                ldsm4(bl, bBase + jj * (16 * 208) + 96 + ks * 32);
                mma_bf16(acc[2 * jj],     ah[ks], bh[0], bh[1]);
                mma_bf16(acc[2 * jj + 1], ah[ks], bh[2], bh[3]);
                mma_bf16(acc[2 * jj],     al[ks], bh[0], bh[1]);
                mma_bf16(acc[2 * jj + 1], al[ks], bh[2], bh[3]);
                mma_bf16(acc[2 * jj],     ah[ks], bl[0], bl[1]);
                mma_bf16(acc[2 * jj + 1], ah[ks], bl[2], bl[3]);
            }
        }
    }

    // ---- GEMM2 (register-fed): C-frag of GEMM1 == A-frag of GEMM2 ----
    float acc2[2][4];
    #pragma unroll
    for (int j = 0; j < 2; j++)
        #pragma unroll
        for (int r = 0; r < 4; r++) acc2[j][r] = 0.f;

    const int c0 = (lane & 3) * 2;
    {
        const float* b1s = (const float*)(sm + SM_B1V);
        const uint32_t b2Base = smb + SM_B2 + ((lane & 7) + ((lane >> 4) & 1) * 8) * 528
                                            + ((lane >> 3) & 1) * 16;
        #pragma unroll
        for (int ks = 0; ks < 8; ks++) {
            int n0 = 16 * ks + c0;
            int n1 = n0 + 8;
            float bn00 = b1s[n0], bn01 = b1s[n0 + 1];
            float bn10 = b1s[n1], bn11 = b1s[n1 + 1];
            float v00 = fmaxf(acc[2 * ks][0] + bn00, 0.f);
            float v01 = fmaxf(acc[2 * ks][1] + bn01, 0.f);
            float v02 = fmaxf(acc[2 * ks][2] + bn00, 0.f);
            float v03 = fmaxf(acc[2 * ks][3] + bn01, 0.f);
            float v10 = fmaxf(acc[2 * ks + 1][0] + bn10, 0.f);
            float v11 = fmaxf(acc[2 * ks + 1][1] + bn11, 0.f);
            float v12 = fmaxf(acc[2 * ks + 1][2] + bn10, 0.f);
            float v13 = fmaxf(acc[2 * ks + 1][3] + bn11, 0.f);
            uint32_t ahi[4], alo[4];
            ahi[0] = pack2(v00, v01);
            ahi[1] = pack2(v02, v03);
            ahi[2] = pack2(v10, v11);
            ahi[3] = pack2(v12, v13);
            alo[0] = pack2(v00 - bf16_val((uint16_t)ahi[0]), v01 - bf16_val((uint16_t)(ahi[0] >> 16)));
            alo[1] = pack2(v02 - bf16_val((uint16_t)ahi[1]), v03 - bf16_val((uint16_t)(ahi[1] >> 16)));
            alo[2] = pack2(v10 - bf16_val((uint16_t)ahi[2]), v11 - bf16_val((uint16_t)(ahi[2] >> 16)));
            alo[3] = pack2(v12 - bf16_val((uint16_t)ahi[3]), v13 - bf16_val((uint16_t)(ahi[3] >> 16)));

            uint32_t bh[4], bl[4];
            ldsm4(bh, b2Base + ks * 32);
            ldsm4(bl, b2Base + 256 + ks * 32);   // W2lo at k=128 -> byte offset 256
            mma_bf16(acc2[0], ahi, bh[0], bh[1]);
            mma_bf16(acc2[1], ahi, bh[2], bh[3]);
            mma_bf16(acc2[0], alo, bh[0], bh[1]);
            mma_bf16(acc2[1], alo, bh[2], bh[3]);
            mma_bf16(acc2[0], ahi, bl[0], bl[1]);
            mma_bf16(acc2[1], ahi, bl[2], bl[3]);
        }
    }

    // ---- epilogue: dx + stochastic update -> g_xnew / alpha arrays ----
    {
        const float* b2s = (const float*)(sm + SM_B2V);
        const int p0 = 16 * w + (lane >> 2);
        float bc0 = b2s[c0], bc1 = b2s[c0 + 1], bc8 = b2s[c0 + 8], bc9 = b2s[c0 + 9];
        #pragma unroll
        for (int px = 0; px < 2; px++) {
            int p = p0 + px * 8;
            float xo0 = XH[(16 + c0)     * 132 + 1 + p];
            float xo1 = XH[(16 + c0 + 1) * 132 + 1 + p];
            float xo2 = XH[(16 + c0 + 8) * 132 + 1 + p];
            float xo3 = XH[(16 + c0 + 9) * 132 + 1 + p];
            size_t pix = (size_t)(b * HH + i) * WW + j0 + p;
            float um = (ru[pix] <= 0.5f) ? 1.f : 0.f;
            float xn0 = xo0 + (acc2[0][2 * px]     + bc0) * um;
            float xn1 = xo1 + (acc2[0][2 * px + 1] + bc1) * um;
            float xn2 = xo2 + (acc2[1][2 * px]     + bc8) * um;
            float xn3 = xo3 + (acc2[1][2 * px + 1] + bc9) * um;
            *(float2*)(g_xnew + pix * 16 + c0)     = make_float2(xn0, xn1);
            *(float2*)(g_xnew + pix * 16 + c0 + 8) = make_float2(xn2, xn3);
            if ((lane & 3) == 1) {                 // c0==2 -> channel 3 = slot 1
                g_aold[pix] = xo1;
                g_anew[pix] = xn1;
            }
        }
    }
}

// ================= Pass 2 ===================================================
__global__ void __launch_bounds__(256) nca_pass2(float* __restrict__ out)
{
    __shared__ float sao[3][256];
    __shared__ float san[3][256];
    const int t   = threadIdx.x;
    const int row = blockIdx.x;
    const int b   = row >> 8;
    const int i   = row & 255;

    size_t pix = (size_t)row * WW + t;
    float4 v0 = ((const float4*)(g_xnew + pix * 16))[0];
    float4 v1 = ((const float4*)(g_xnew + pix * 16))[1];
    float4 v2 = ((const float4*)(g_xnew + pix * 16))[2];
    float4 v3 = ((const float4*)(g_xnew + pix * 16))[3];

    #pragma unroll
    for (int rr = 0; rr < 3; rr++) {
        int gi = i + rr - 1;
        float vo = -1e30f, vn = -1e30f;
        if (gi >= 0 && gi < HH) {
            size_t idx = (size_t)(b * HH + gi) * WW + t;
            vo = g_aold[idx];
            vn = g_anew[idx];
        }
        sao[rr][t] = vo;
        san[rr][t] = vn;
    }
    __syncthreads();

    float mo = -1e30f, mn = -1e30f;
    #pragma unroll
    for (int rr = 0; rr < 3; rr++) {
        #pragma unroll
        for (int dc = 0; dc < 3; dc++) {
            int jc = t + dc - 1;
            if (jc >= 0 && jc < WW) {
                mo = fmaxf(mo, sao[rr][jc]);
                mn = fmaxf(mn, san[rr][jc]);
            }
        }
    }
    float mask = (mo > 0.1f && mn > 0.1f) ? 1.f : 0.f;

    float4* dst = (float4*)(out + pix * 16);
    v0.x *= mask; v0.y *= mask; v0.z *= mask; v0.w *= mask;
    v1.x *= mask; v1.y *= mask; v1.z *= mask; v1.w *= mask;
    v2.x *= mask; v2.y *= mask; v2.z *= mask; v2.w *= mask;
    v3.x *= mask; v3.y *= mask; v3.z *= mask; v3.w *= mask;
    dst[0] = v0; dst[1] = v1; dst[2] = v2; dst[3] = v3;
}

extern "C" void kernel_launch(void* const* d_in, const int* in_sizes, int n_in,
                              void* d_out, int out_size)
{
    const float *x = nullptr, *W1 = nullptr, *b1 = nullptr,
                *W2 = nullptr, *b2 = nullptr, *ru = nullptr;
    for (int k = 0; k < n_in; k++) {
        switch (in_sizes[k]) {
            case 16777216: x  = (const float*)d_in[k]; break;
            case 6144:     W1 = (const float*)d_in[k]; break;
            case 128:      b1 = (const float*)d_in[k]; break;
            case 2048:     W2 = (const float*)d_in[k]; break;
            case 16:       b2 = (const float*)d_in[k]; break;
            case 1048576:  ru = (const float*)d_in[k]; break;
            default: break;
        }
    }
    float* out = (float*)d_out;

    cudaFuncSetAttribute(nca_pass1, cudaFuncAttributeMaxDynamicSharedMemorySize, SMEM_BYTES);
    nca_prep<<<24, 256>>>(W1, W2);
    nca_pass1<<<8192, 256, SMEM_BYTES>>>(x, b1, b2, ru);
    nca_pass2<<<4096, 256>>>(out);
}

// round 7
// speedup vs baseline: 1.5272x; 1.0656x over previous
#include <cuda_runtime.h>
#include <cuda_bf16.h>
#include <cstdint>

#define BATCH 16
#define HH 256
#define WW 256
#define NPIX (BATCH*HH*WW)

// ---- scratch (__device__ globals; no allocs allowed) ----
__device__ float g_xnew[(size_t)NPIX * 16];   // 64MB
__device__ float g_aold[NPIX];                // 4MB
__device__ float g_anew[NPIX];                // 4MB
__device__ __align__(16) unsigned char g_B1[128 * 104 * 2];  // bf16 [128n][104k] (96 used: hi|lo)
__device__ __align__(16) unsigned char g_B2[16 * 264 * 2];   // bf16 [16n][264k] (256 used: hi|lo)

// ================= warp-MMA helpers =================
__device__ __forceinline__ uint32_t smem_u32(const void* p) {
    uint32_t a;
    asm("{ .reg .u64 t; cvta.to.shared.u64 t, %1; cvt.u32.u64 %0, t; }" : "=r"(a) : "l"(p));
    return a;
}
__device__ __forceinline__ void ldsm4(uint32_t* r, uint32_t addr) {
    asm volatile("ldmatrix.sync.aligned.m8n8.x4.shared.b16 {%0,%1,%2,%3}, [%4];"
        : "=r"(r[0]), "=r"(r[1]), "=r"(r[2]), "=r"(r[3]) : "r"(addr));
}
__device__ __forceinline__ void mma_bf16(float* d, const uint32_t* a, uint32_t b0, uint32_t b1) {
    asm volatile("mma.sync.aligned.m16n8k16.row.col.f32.bf16.bf16.f32 "
        "{%0,%1,%2,%3}, {%4,%5,%6,%7}, {%8,%9}, {%0,%1,%2,%3};"
        : "+f"(d[0]), "+f"(d[1]), "+f"(d[2]), "+f"(d[3])
        : "r"(a[0]), "r"(a[1]), "r"(a[2]), "r"(a[3]), "r"(b0), "r"(b1));
}
__device__ __forceinline__ uint16_t bf16_bits(float f) {
    return __bfloat16_as_ushort(__float2bfloat16(f));
}
__device__ __forceinline__ float bf16_val(uint16_t u) {
    return __bfloat162float(__ushort_as_bfloat16(u));
}
__device__ __forceinline__ uint32_t pack2(float a, float b) {
    return (uint32_t)bf16_bits(a) | ((uint32_t)bf16_bits(b) << 16);
}

// ================= prep: bf16 hi/lo weight tile images (multi-CTA) ==========
__global__ void nca_prep(const float* __restrict__ W1, const float* __restrict__ W2)
{
    int q = blockIdx.x * 256 + threadIdx.x;    // 24 x 256 = 6144 threads
    __nv_bfloat16* B1 = (__nv_bfloat16*)g_B1;
    __nv_bfloat16* B2 = (__nv_bfloat16*)g_B2;
    if (q < 6144) {                            // W1 [48k][128n]
        int k = q >> 7, n = q & 127;
        float v = W1[q];
        __nv_bfloat16 h = __float2bfloat16(v);
        B1[n * 104 + k]      = h;
        B1[n * 104 + 48 + k] = __float2bfloat16(v - __bfloat162float(h));
    }
    if (q < 2048) {                            // W2 [128d][16c]
        int d = q >> 4, c = q & 15;
        float v = W2[q];
        __nv_bfloat16 h = __float2bfloat16(v);
        B2[c * 264 + d]       = h;
        B2[c * 264 + 128 + d] = __float2bfloat16(v - __bfloat162float(h));
    }
}

// ================= Pass 1 ===================================================
// CTA = 128 pixels (half row), 256 threads / 8 warps. Warp w owns pixels
// [16w, 16w+16). Split-bf16 3 terms: Ahi*Bhi + Alo*Bhi + Ahi*Blo.
//
// SMEM (bytes):
//   A1  @ 0      : bf16 [128 px][104]  (k: hi 0:48 | lo 48:96)  = 26624
//   B1  @ 26624  : bf16 [128 n][104]   = 26624
//   B2  @ 53248  : bf16 [16 n][264]    (W2hi 0:128 | W2lo 128:256) = 8448
//   XH  @ 61696  : f32 [3 rows][132 cols][20 ch-slots] (pixel-major!) = 31680
//   b1v @ 93376  : f32[128] = 512
//   b2v @ 93888  : f32[16]  = 64
#define SM_A1   0
#define SM_B1   26624
#define SM_B2   53248
#define SM_XH   61696
#define SM_B1V  93376
#define SM_B2V  93888
#define SMEM_BYTES 93952

#define XH_F(rr, cc, c) (((rr) * 132 + (cc)) * 20 + (c))

extern __shared__ unsigned char sm[];

__global__ void __launch_bounds__(256, 2) nca_pass1(
    const float* __restrict__ x,  const float* __restrict__ b1,
    const float* __restrict__ b2, const float* __restrict__ ru)
{
    const uint32_t smb = smem_u32(sm);
    float* XH = (float*)(sm + SM_XH);

    const int t    = threadIdx.x;
    const int w    = t >> 5;
    const int lane = t & 31;
    const int bid  = blockIdx.x;
    const int tile = bid & 1;
    const int row  = bid >> 1;
    const int b    = row >> 8;
    const int i    = row & 255;
    const int j0   = tile << 7;

    // ---- cooperative tile copies (L2-hot) + bias loads ----
    for (int q = t; q < 1664; q += 256)
        ((float4*)(sm + SM_B1))[q] = ((const float4*)g_B1)[q];
    for (int q = t; q < 528; q += 256)
        ((float4*)(sm + SM_B2))[q] = ((const float4*)g_B2)[q];
    if (t < 128) ((float*)(sm + SM_B1V))[t] = b1[t];
    if (t < 16)  ((float*)(sm + SM_B2V))[t] = b2[t];

    // ---- x-halo: 3 rows x 130 cols x 16 ch -> pixel-major XH (direct f4 store)
    for (int task = t; task < 1560; task += 256) {
        int rr  = task / 520;
        int rem = task - rr * 520;
        int cc  = rem >> 2;
        int cg  = rem & 3;
        int gi  = i + rr - 1;
        int jc  = j0 + cc - 1;
        float4 v = make_float4(0.f, 0.f, 0.f, 0.f);
        if (gi >= 0 && gi < HH && jc >= 0 && jc < WW)
            v = *(const float4*)(x + (((size_t)(b * HH + gi) * WW + jc) << 4) + (cg << 2));
        *(float4*)(XH + XH_F(rr, cc, cg * 4)) = v;
    }
    __syncthreads();

    // ---- perceive: thread = (pixel pp, channel-half g). 18 LDS.128 in,
    //      24 hi + 24 lo bf16 out as 6 STS.128 (conflict-free both ways) ----
    {
        const int pp = t & 127;
        const int g  = t >> 7;               // channels 8g .. 8g+7
        float4 v[3][3][2];
        #pragma unroll
        for (int rr = 0; rr < 3; rr++)
            #pragma unroll
            for (int cx = 0; cx < 3; cx++) {
                const float* base = XH + XH_F(rr, pp + cx, 8 * g);
                v[rr][cx][0] = *(const float4*)(base);
                v[rr][cx][1] = *(const float4*)(base + 4);
            }

        uint32_t hi[12], lo[12];
        #pragma unroll
        for (int cq = 0; cq < 8; cq++) {
            const int h = cq >> 2, e = cq & 3;
            float a00 = ((const float*)&v[0][0][h])[e];
            float a01 = ((const float*)&v[0][1][h])[e];
            float a02 = ((const float*)&v[0][2][h])[e];
            float a10 = ((const float*)&v[1][0][h])[e];
            float a11 = ((const float*)&v[1][1][h])[e];
            float a12 = ((const float*)&v[1][2][h])[e];
            float a20 = ((const float*)&v[2][0][h])[e];
            float a21 = ((const float*)&v[2][1][h])[e];
            float a22 = ((const float*)&v[2][2][h])[e];
            float yv[3];
            yv[0] = a11;
            yv[1] = ((a02 + 2.f * a12 + a22) - (a00 + 2.f * a10 + a20)) * 0.125f;
            yv[2] = ((a20 + 2.f * a21 + a22) - (a00 + 2.f * a01 + a02)) * 0.125f;
            #pragma unroll
            for (int e2 = 0; e2 < 3; e2++) {
                int m = 3 * cq + e2;          // 0..23
                uint16_t hb = bf16_bits(yv[e2]);
                uint16_t lb = bf16_bits(yv[e2] - bf16_val(hb));
                if (m & 1) { hi[m >> 1] |= (uint32_t)hb << 16; lo[m >> 1] |= (uint32_t)lb << 16; }
                else       { hi[m >> 1]  = (uint32_t)hb;       lo[m >> 1]  = (uint32_t)lb; }
            }
        }
        // A1 row pp: hi at bytes [48g, 48g+48), lo at [96+48g, 96+48g+48)
        unsigned char* rowp = sm + SM_A1 + pp * 208;
        #pragma unroll
        for (int q = 0; q < 3; q++) {
            *(uint4*)(rowp + 48 * g + 16 * q)      = *(uint4*)(hi + 4 * q);
            *(uint4*)(rowp + 96 + 48 * g + 16 * q) = *(uint4*)(lo + 4 * q);
        }
    }
    __syncthreads();

    // ---- prefetch ru for this thread's epilogue pixels (hide DRAM latency) --
    const int c0 = (lane & 3) * 2;
    const int p0 = 16 * w + (lane >> 2);
    const size_t pixbase = (size_t)(b * HH + i) * WW + j0;
    float u0 = ru[pixbase + p0];
    float u1 = ru[pixbase + p0 + 8];

    // ---- GEMM1: acc[16 n8-tiles][4] = A1[16w..][96] x B1 (3 terms) ----
    float acc[16][4];
    #pragma unroll
    for (int j = 0; j < 16; j++)
        #pragma unroll
        for (int r = 0; r < 4; r++) acc[j][r] = 0.f;

    uint32_t ah[3][4], al[3][4];
    {
        const uint32_t aBase = smb + SM_A1 + (16 * w + (lane & 15)) * 208 + (lane >> 4) * 16;
        #pragma unroll
        for (int ks = 0; ks < 3; ks++) {
            ldsm4(ah[ks], aBase + ks * 32);
            ldsm4(al[ks], aBase + 96 + ks * 32);
        }
        const uint32_t bBase = smb + SM_B1 + ((lane & 7) + ((lane >> 4) & 1) * 8) * 208
                                           + ((lane >> 3) & 1) * 16;
        #pragma unroll
        for (int jj = 0; jj < 8; jj++) {
            #pragma unroll
            for (int ks = 0; ks < 3; ks++) {
                uint32_t bh[4], bl[4];
                ldsm4(bh, bBase + jj * (16 * 208) + ks * 32);
                ldsm4(bl, bBase + jj * (16 * 208) + 96 + ks * 32);
                mma_bf16(acc[2 * jj],     ah[ks], bh[0], bh[1]);
                mma_bf16(acc[2 * jj + 1], ah[ks], bh[2], bh[3]);
                mma_bf16(acc[2 * jj],     al[ks], bh[0], bh[1]);
                mma_bf16(acc[2 * jj + 1], al[ks], bh[2], bh[3]);
                mma_bf16(acc[2 * jj],     ah[ks], bl[0], bl[1]);
                mma_bf16(acc[2 * jj + 1], ah[ks], bl[2], bl[3]);
            }
        }
    }

    // ---- GEMM2 (register-fed): C-frag of GEMM1 == A-frag of GEMM2 ----
    float acc2[2][4];
    #pragma unroll
    for (int j = 0; j < 2; j++)
        #pragma unroll
        for (int r = 0; r < 4; r++) acc2[j][r] = 0.f;

    {
        const float* b1s = (const float*)(sm + SM_B1V);
        const uint32_t b2Base = smb + SM_B2 + ((lane & 7) + ((lane >> 4) & 1) * 8) * 528
                                            + ((lane >> 3) & 1) * 16;
        #pragma unroll
        for (int ks = 0; ks < 8; ks++) {
            int n0 = 16 * ks + c0;
            int n1 = n0 + 8;
            float bn00 = b1s[n0], bn01 = b1s[n0 + 1];
            float bn10 = b1s[n1], bn11 = b1s[n1 + 1];
            float v00 = fmaxf(acc[2 * ks][0] + bn00, 0.f);
            float v01 = fmaxf(acc[2 * ks][1] + bn01, 0.f);
            float v02 = fmaxf(acc[2 * ks][2] + bn00, 0.f);
            float v03 = fmaxf(acc[2 * ks][3] + bn01, 0.f);
            float v10 = fmaxf(acc[2 * ks + 1][0] + bn10, 0.f);
            float v11 = fmaxf(acc[2 * ks + 1][1] + bn11, 0.f);
            float v12 = fmaxf(acc[2 * ks + 1][2] + bn10, 0.f);
            float v13 = fmaxf(acc[2 * ks + 1][3] + bn11, 0.f);
            uint32_t ahi[4], alo[4];
            ahi[0] = pack2(v00, v01);
            ahi[1] = pack2(v02, v03);
            ahi[2] = pack2(v10, v11);
            ahi[3] = pack2(v12, v13);
            alo[0] = pack2(v00 - bf16_val((uint16_t)ahi[0]), v01 - bf16_val((uint16_t)(ahi[0] >> 16)));
            alo[1] = pack2(v02 - bf16_val((uint16_t)ahi[1]), v03 - bf16_val((uint16_t)(ahi[1] >> 16)));
            alo[2] = pack2(v10 - bf16_val((uint16_t)ahi[2]), v11 - bf16_val((uint16_t)(ahi[2] >> 16)));
            alo[3] = pack2(v12 - bf16_val((uint16_t)ahi[3]), v13 - bf16_val((uint16_t)(ahi[3] >> 16)));

            uint32_t bh[4], bl[4];
            ldsm4(bh, b2Base + ks * 32);
            ldsm4(bl, b2Base + 256 + ks * 32);   // W2lo at k=128 -> byte offset 256
            mma_bf16(acc2[0], ahi, bh[0], bh[1]);
            mma_bf16(acc2[1], ahi, bh[2], bh[3]);
            mma_bf16(acc2[0], alo, bh[0], bh[1]);
            mma_bf16(acc2[1], alo, bh[2], bh[3]);
            mma_bf16(acc2[0], ahi, bl[0], bl[1]);
            mma_bf16(acc2[1], ahi, bl[2], bl[3]);
        }
    }

    // ---- epilogue: dx + stochastic update -> g_xnew / alpha arrays ----
    {
        const float* b2s = (const float*)(sm + SM_B2V);
        float bc0 = b2s[c0], bc1 = b2s[c0 + 1], bc8 = b2s[c0 + 8], bc9 = b2s[c0 + 9];
        #pragma unroll
        for (int px = 0; px < 2; px++) {
            int p = p0 + px * 8;
            const float* xo = XH + XH_F(1, p + 1, 0);
            float xo0 = xo[c0],     xo1 = xo[c0 + 1];
            float xo2 = xo[c0 + 8], xo3 = xo[c0 + 9];
            size_t pix = pixbase + p;
            float um = ((px ? u1 : u0) <= 0.5f) ? 1.f : 0.f;
            float xn0 = xo0 + (acc2[0][2 * px]     + bc0) * um;
            float xn1 = xo1 + (acc2[0][2 * px + 1] + bc1) * um;
            float xn2 = xo2 + (acc2[1][2 * px]     + bc8) * um;
            float xn3 = xo3 + (acc2[1][2 * px + 1] + bc9) * um;
            *(float2*)(g_xnew + pix * 16 + c0)     = make_float2(xn0, xn1);
            *(float2*)(g_xnew + pix * 16 + c0 + 8) = make_float2(xn2, xn3);
            if ((lane & 3) == 1) {                 // c0==2 -> channel 3 = slot 1
                g_aold[pix] = xo1;
                g_anew[pix] = xn1;
            }
        }
    }
}

// ================= Pass 2 ===================================================
__global__ void __launch_bounds__(256) nca_pass2(float* __restrict__ out)
{
    __shared__ float sao[3][256];
    __shared__ float san[3][256];
    const int t   = threadIdx.x;
    const int row = blockIdx.x;
    const int b   = row >> 8;
    const int i   = row & 255;

    size_t pix = (size_t)row * WW + t;
    float4 v0 = ((const float4*)(g_xnew + pix * 16))[0];
    float4 v1 = ((const float4*)(g_xnew + pix * 16))[1];
    float4 v2 = ((const float4*)(g_xnew + pix * 16))[2];
    float4 v3 = ((const float4*)(g_xnew + pix * 16))[3];

    #pragma unroll
    for (int rr = 0; rr < 3; rr++) {
        int gi = i + rr - 1;
        float vo = -1e30f, vn = -1e30f;
        if (gi >= 0 && gi < HH) {
            size_t idx = (size_t)(b * HH + gi) * WW + t;
            vo = g_aold[idx];
            vn = g_anew[idx];
        }
        sao[rr][t] = vo;
        san[rr][t] = vn;
    }
    __syncthreads();

    float mo = -1e30f, mn = -1e30f;
    #pragma unroll
    for (int rr = 0; rr < 3; rr++) {
        #pragma unroll
        for (int dc = 0; dc < 3; dc++) {
            int jc = t + dc - 1;
            if (jc >= 0 && jc < WW) {
                mo = fmaxf(mo, sao[rr][jc]);
                mn = fmaxf(mn, san[rr][jc]);
            }
        }
    }
    float mask = (mo > 0.1f && mn > 0.1f) ? 1.f : 0.f;

    float4* dst = (float4*)(out + pix * 16);
    v0.x *= mask; v0.y *= mask; v0.z *= mask; v0.w *= mask;
    v1.x *= mask; v1.y *= mask; v1.z *= mask; v1.w *= mask;
    v2.x *= mask; v2.y *= mask; v2.z *= mask; v2.w *= mask;
    v3.x *= mask; v3.y *= mask; v3.z *= mask; v3.w *= mask;
    dst[0] = v0; dst[1] = v1; dst[2] = v2; dst[3] = v3;
}

extern "C" void kernel_launch(void* const* d_in, const int* in_sizes, int n_in,
                              void* d_out, int out_size)
{
    const float *x = nullptr, *W1 = nullptr, *b1 = nullptr,
                *W2 = nullptr, *b2 = nullptr, *ru = nullptr;
    for (int k = 0; k < n_in; k++) {
        switch (in_sizes[k]) {
            case 16777216: x  = (const float*)d_in[k]; break;
            case 6144:     W1 = (const float*)d_in[k]; break;
            case 128:      b1 = (const float*)d_in[k]; break;
            case 2048:     W2 = (const float*)d_in[k]; break;
            case 16:       b2 = (const float*)d_in[k]; break;
            case 1048576:  ru = (const float*)d_in[k]; break;
            default: break;
        }
    }
    float* out = (float*)d_out;

    cudaFuncSetAttribute(nca_pass1, cudaFuncAttributeMaxDynamicSharedMemorySize, SMEM_BYTES);
    nca_prep<<<24, 256>>>(W1, W2);
    nca_pass1<<<8192, 256, SMEM_BYTES>>>(x, b1, b2, ru);
    nca_pass2<<<4096, 256>>>(out);
}

// round 8
// speedup vs baseline: 1.8235x; 1.1940x over previous
#include <cuda_runtime.h>
#include <cuda_fp16.h>
#include <cstdint>

#define BATCH 16
#define HH 256
#define WW 256
#define NPIX (BATCH*HH*WW)

// ---- scratch (__device__ globals; no allocs allowed) ----
__device__ float g_aold[NPIX];                // 4MB
__device__ float g_anew[NPIX];                // 4MB
__device__ __align__(16) unsigned char g_B1[128 * 104 * 2];  // f16 [128n][104k] (hi 0:48 | lo 48:96)
__device__ __align__(16) unsigned char g_B2[16 * 264 * 2];   // f16 [16n][264k] (hi 0:128 | lo 128:256)

// ================= warp-MMA helpers =================
__device__ __forceinline__ uint32_t smem_u32(const void* p) {
    uint32_t a;
    asm("{ .reg .u64 t; cvta.to.shared.u64 t, %1; cvt.u32.u64 %0, t; }" : "=r"(a) : "l"(p));
    return a;
}
__device__ __forceinline__ void ldsm4(uint32_t* r, uint32_t addr) {
    asm volatile("ldmatrix.sync.aligned.m8n8.x4.shared.b16 {%0,%1,%2,%3}, [%4];"
        : "=r"(r[0]), "=r"(r[1]), "=r"(r[2]), "=r"(r[3]) : "r"(addr));
}
__device__ __forceinline__ void mma_f16(float* d, const uint32_t* a, uint32_t b0, uint32_t b1) {
    asm volatile("mma.sync.aligned.m16n8k16.row.col.f32.f16.f16.f32 "
        "{%0,%1,%2,%3}, {%4,%5,%6,%7}, {%8,%9}, {%0,%1,%2,%3};"
        : "+f"(d[0]), "+f"(d[1]), "+f"(d[2]), "+f"(d[3])
        : "r"(a[0]), "r"(a[1]), "r"(a[2]), "r"(a[3]), "r"(b0), "r"(b1));
}
__device__ __forceinline__ uint16_t f16_bits(float f) {
    return __half_as_ushort(__float2half(f));
}
__device__ __forceinline__ float f16_val(uint16_t u) {
    return __half2float(__ushort_as_half(u));
}
__device__ __forceinline__ uint32_t pack2(float a, float b) {
    return (uint32_t)f16_bits(a) | ((uint32_t)f16_bits(b) << 16);
}

// ================= prep: f16 hi/lo weight tile images (multi-CTA) ==========
__global__ void nca_prep(const float* __restrict__ W1, const float* __restrict__ W2)
{
    int q = blockIdx.x * 256 + threadIdx.x;    // 24 x 256 = 6144 threads
    __half* B1 = (__half*)g_B1;
    __half* B2 = (__half*)g_B2;
    if (q < 6144) {                            // W1 [48k][128n]
        int k = q >> 7, n = q & 127;
        float v = W1[q];
        __half h = __float2half(v);
        B1[n * 104 + k]      = h;
        B1[n * 104 + 48 + k] = __float2half(v - __half2float(h));
    }
    if (q < 2048) {                            // W2 [128d][16c]
        int d = q >> 4, c = q & 15;
        float v = W2[q];
        __half h = __float2half(v);
        B2[c * 264 + d]       = h;
        B2[c * 264 + 128 + d] = __float2half(v - __half2float(h));
    }
}

// ================= Pass 1 ===================================================
// CTA = 128 pixels (half row), 256 threads / 8 warps. Warp w owns pixels
// [16w, 16w+16). fp16 2-term split: Ahi*Bhi + Alo*Bhi (A-residual compensated;
// B-residual ~2^-11 dropped -> ~1e-4 final rel_err).
//
// SMEM (bytes):
//   A1  @ 0      : f16 [128 px][104]  (hi 0:48 | lo 48:96)  = 26624
//   B1  @ 26624  : f16 [128 n][104]   = 26624
//   B2  @ 53248  : f16 [16 n][264]    = 8448
//   XH  @ 61696  : f32 [3][132][20] pixel-major = 31680
//   b1v @ 93376  : f32[128] = 512
//   b2v @ 93888  : f32[16]  = 64
#define SM_A1   0
#define SM_B1   26624
#define SM_B2   53248
#define SM_XH   61696
#define SM_B1V  93376
#define SM_B2V  93888
#define SMEM_BYTES 93952

#define XH_F(rr, cc, c) (((rr) * 132 + (cc)) * 20 + (c))

extern __shared__ unsigned char sm[];

__global__ void __launch_bounds__(256, 2) nca_pass1(
    const float* __restrict__ x,  const float* __restrict__ b1,
    const float* __restrict__ b2, const float* __restrict__ ru,
    float* __restrict__ out)
{
    const uint32_t smb = smem_u32(sm);
    float* XH = (float*)(sm + SM_XH);

    const int t    = threadIdx.x;
    const int w    = t >> 5;
    const int lane = t & 31;
    const int bid  = blockIdx.x;
    const int tile = bid & 1;
    const int row  = bid >> 1;
    const int b    = row >> 8;
    const int i    = row & 255;
    const int j0   = tile << 7;

    // ---- cooperative tile copies (L2-hot) + bias loads ----
    for (int q = t; q < 1664; q += 256)
        ((float4*)(sm + SM_B1))[q] = ((const float4*)g_B1)[q];
    for (int q = t; q < 528; q += 256)
        ((float4*)(sm + SM_B2))[q] = ((const float4*)g_B2)[q];
    if (t < 128) ((float*)(sm + SM_B1V))[t] = b1[t];
    if (t < 16)  ((float*)(sm + SM_B2V))[t] = b2[t];

    // ---- x-halo: 3 rows x 130 cols x 16 ch -> pixel-major XH (direct f4 store)
    for (int task = t; task < 1560; task += 256) {
        int rr  = task / 520;
        int rem = task - rr * 520;
        int cc  = rem >> 2;
        int cg  = rem & 3;
        int gi  = i + rr - 1;
        int jc  = j0 + cc - 1;
        float4 v = make_float4(0.f, 0.f, 0.f, 0.f);
        if (gi >= 0 && gi < HH && jc >= 0 && jc < WW)
            v = *(const float4*)(x + (((size_t)(b * HH + gi) * WW + jc) << 4) + (cg << 2));
        *(float4*)(XH + XH_F(rr, cc, cg * 4)) = v;
    }
    __syncthreads();

    // ---- perceive: thread = (pixel pp, channel-half g); wide conflict-free ops
    {
        const int pp = t & 127;
        const int g  = t >> 7;               // channels 8g .. 8g+7
        float4 v[3][3][2];
        #pragma unroll
        for (int rr = 0; rr < 3; rr++)
            #pragma unroll
            for (int cx = 0; cx < 3; cx++) {
                const float* base = XH + XH_F(rr, pp + cx, 8 * g);
                v[rr][cx][0] = *(const float4*)(base);
                v[rr][cx][1] = *(const float4*)(base + 4);
            }

        uint32_t hi[12], lo[12];
        #pragma unroll
        for (int cq = 0; cq < 8; cq++) {
            const int h = cq >> 2, e = cq & 3;
            float a00 = ((const float*)&v[0][0][h])[e];
            float a01 = ((const float*)&v[0][1][h])[e];
            float a02 = ((const float*)&v[0][2][h])[e];
            float a10 = ((const float*)&v[1][0][h])[e];
            float a11 = ((const float*)&v[1][1][h])[e];
            float a12 = ((const float*)&v[1][2][h])[e];
            float a20 = ((const float*)&v[2][0][h])[e];
            float a21 = ((const float*)&v[2][1][h])[e];
            float a22 = ((const float*)&v[2][2][h])[e];
            float yv[3];
            yv[0] = a11;
            yv[1] = ((a02 + 2.f * a12 + a22) - (a00 + 2.f * a10 + a20)) * 0.125f;
            yv[2] = ((a20 + 2.f * a21 + a22) - (a00 + 2.f * a01 + a02)) * 0.125f;
            #pragma unroll
            for (int e2 = 0; e2 < 3; e2++) {
                int m = 3 * cq + e2;          // 0..23
                uint16_t hb = f16_bits(yv[e2]);
                uint16_t lb = f16_bits(yv[e2] - f16_val(hb));
                if (m & 1) { hi[m >> 1] |= (uint32_t)hb << 16; lo[m >> 1] |= (uint32_t)lb << 16; }
                else       { hi[m >> 1]  = (uint32_t)hb;       lo[m >> 1]  = (uint32_t)lb; }
            }
        }
        unsigned char* rowp = sm + SM_A1 + pp * 208;
        #pragma unroll
        for (int q = 0; q < 3; q++) {
            *(uint4*)(rowp + 48 * g + 16 * q)      = *(uint4*)(hi + 4 * q);
            *(uint4*)(rowp + 96 + 48 * g + 16 * q) = *(uint4*)(lo + 4 * q);
        }
    }
    __syncthreads();

    // ---- prefetch ru for epilogue pixels (hide DRAM latency under MMA) ----
    const int c0 = (lane & 3) * 2;
    const int p0 = 16 * w + (lane >> 2);
    const size_t pixbase = (size_t)(b * HH + i) * WW + j0;
    float u0 = ru[pixbase + p0];
    float u1 = ru[pixbase + p0 + 8];

    // ---- GEMM1: acc[16 n8-tiles][4] = A1[16w..][48] x B1hi (2 terms) ----
    float acc[16][4];
    #pragma unroll
    for (int j = 0; j < 16; j++)
        #pragma unroll
        for (int r = 0; r < 4; r++) acc[j][r] = 0.f;

    uint32_t ah[3][4], al[3][4];
    {
        const uint32_t aBase = smb + SM_A1 + (16 * w + (lane & 15)) * 208 + (lane >> 4) * 16;
        #pragma unroll
        for (int ks = 0; ks < 3; ks++) {
            ldsm4(ah[ks], aBase + ks * 32);
            ldsm4(al[ks], aBase + 96 + ks * 32);
        }
        const uint32_t bBase = smb + SM_B1 + ((lane & 7) + ((lane >> 4) & 1) * 8) * 208
                                           + ((lane >> 3) & 1) * 16;
        #pragma unroll
        for (int jj = 0; jj < 8; jj++) {
            #pragma unroll
            for (int ks = 0; ks < 3; ks++) {
                uint32_t bh[4];
                ldsm4(bh, bBase + jj * (16 * 208) + ks * 32);
                mma_f16(acc[2 * jj],     ah[ks], bh[0], bh[1]);
                mma_f16(acc[2 * jj + 1], ah[ks], bh[2], bh[3]);
                mma_f16(acc[2 * jj],     al[ks], bh[0], bh[1]);
                mma_f16(acc[2 * jj + 1], al[ks], bh[2], bh[3]);
            }
        }
    }

    // ---- GEMM2 (register-fed): h = relu(acc+b1) split hi/lo; 2-term ----
    float acc2[2][4];
    #pragma unroll
    for (int j = 0; j < 2; j++)
        #pragma unroll
        for (int r = 0; r < 4; r++) acc2[j][r] = 0.f;

    {
        const float* b1s = (const float*)(sm + SM_B1V);
        const uint32_t b2Base = smb + SM_B2 + ((lane & 7) + ((lane >> 4) & 1) * 8) * 528
                                            + ((lane >> 3) & 1) * 16;
        #pragma unroll
        for (int ks = 0; ks < 8; ks++) {
            int n0 = 16 * ks + c0;
            int n1 = n0 + 8;
            float bn00 = b1s[n0], bn01 = b1s[n0 + 1];
            float bn10 = b1s[n1], bn11 = b1s[n1 + 1];
            float v00 = fmaxf(acc[2 * ks][0] + bn00, 0.f);
            float v01 = fmaxf(acc[2 * ks][1] + bn01, 0.f);
            float v02 = fmaxf(acc[2 * ks][2] + bn00, 0.f);
            float v03 = fmaxf(acc[2 * ks][3] + bn01, 0.f);
            float v10 = fmaxf(acc[2 * ks + 1][0] + bn10, 0.f);
            float v11 = fmaxf(acc[2 * ks + 1][1] + bn11, 0.f);
            float v12 = fmaxf(acc[2 * ks + 1][2] + bn10, 0.f);
            float v13 = fmaxf(acc[2 * ks + 1][3] + bn11, 0.f);
            uint32_t ahi[4], alo[4];
            ahi[0] = pack2(v00, v01);
            ahi[1] = pack2(v02, v03);
            ahi[2] = pack2(v10, v11);
            ahi[3] = pack2(v12, v13);
            alo[0] = pack2(v00 - f16_val((uint16_t)ahi[0]), v01 - f16_val((uint16_t)(ahi[0] >> 16)));
            alo[1] = pack2(v02 - f16_val((uint16_t)ahi[1]), v03 - f16_val((uint16_t)(ahi[1] >> 16)));
            alo[2] = pack2(v10 - f16_val((uint16_t)ahi[2]), v11 - f16_val((uint16_t)(ahi[2] >> 16)));
            alo[3] = pack2(v12 - f16_val((uint16_t)ahi[3]), v13 - f16_val((uint16_t)(ahi[3] >> 16)));

            uint32_t bh[4];
            ldsm4(bh, b2Base + ks * 32);
            mma_f16(acc2[0], ahi, bh[0], bh[1]);
            mma_f16(acc2[1], ahi, bh[2], bh[3]);
            mma_f16(acc2[0], alo, bh[0], bh[1]);
            mma_f16(acc2[1], alo, bh[2], bh[3]);
        }
    }

    // ---- epilogue: dx + stochastic update -> out (unmasked) + alpha arrays --
    {
        const float* b2s = (const float*)(sm + SM_B2V);
        float bc0 = b2s[c0], bc1 = b2s[c0 + 1], bc8 = b2s[c0 + 8], bc9 = b2s[c0 + 9];
        #pragma unroll
        for (int px = 0; px < 2; px++) {
            int p = p0 + px * 8;
            const float* xo = XH + XH_F(1, p + 1, 0);
            float xo0 = xo[c0],     xo1 = xo[c0 + 1];
            float xo2 = xo[c0 + 8], xo3 = xo[c0 + 9];
            size_t pix = pixbase + p;
            float um = ((px ? u1 : u0) <= 0.5f) ? 1.f : 0.f;
            float xn0 = xo0 + (acc2[0][2 * px]     + bc0) * um;
            float xn1 = xo1 + (acc2[0][2 * px + 1] + bc1) * um;
            float xn2 = xo2 + (acc2[1][2 * px]     + bc8) * um;
            float xn3 = xo3 + (acc2[1][2 * px + 1] + bc9) * um;
            *(float2*)(out + pix * 16 + c0)     = make_float2(xn0, xn1);
            *(float2*)(out + pix * 16 + c0 + 8) = make_float2(xn2, xn3);
            if ((lane & 3) == 1) {                 // c0==2 -> channel 3 = slot 1
                g_aold[pix] = xo1;
                g_anew[pix] = xn1;
            }
        }
    }
}

// ================= Pass 2: zero the dead pixels only =========================
__global__ void __launch_bounds__(256) nca_pass2(float* __restrict__ out)
{
    __shared__ float sao[3][256];
    __shared__ float san[3][256];
    const int t   = threadIdx.x;
    const int row = blockIdx.x;
    const int b   = row >> 8;
    const int i   = row & 255;

    #pragma unroll
    for (int rr = 0; rr < 3; rr++) {
        int gi = i + rr - 1;
        float vo = -1e30f, vn = -1e30f;
        if (gi >= 0 && gi < HH) {
            size_t idx = (size_t)(b * HH + gi) * WW + t;
            vo = g_aold[idx];
            vn = g_anew[idx];
        }
        sao[rr][t] = vo;
        san[rr][t] = vn;
    }
    __syncthreads();

    float mo = -1e30f, mn = -1e30f;
    #pragma unroll
    for (int rr = 0; rr < 3; rr++) {
        #pragma unroll
        for (int dc = 0; dc < 3; dc++) {
            int jc = t + dc - 1;
            if (jc >= 0 && jc < WW) {
                mo = fmaxf(mo, sao[rr][jc]);
                mn = fmaxf(mn, san[rr][jc]);
            }
        }
    }
    if (!(mo > 0.1f && mn > 0.1f)) {
        size_t pix = (size_t)row * WW + t;
        float4 z = make_float4(0.f, 0.f, 0.f, 0.f);
        float4* dst = (float4*)(out + pix * 16);
        dst[0] = z; dst[1] = z; dst[2] = z; dst[3] = z;
    }
}

extern "C" void kernel_launch(void* const* d_in, const int* in_sizes, int n_in,
                              void* d_out, int out_size)
{
    const float *x = nullptr, *W1 = nullptr, *b1 = nullptr,
                *W2 = nullptr, *b2 = nullptr, *ru = nullptr;
    for (int k = 0; k < n_in; k++) {
        switch (in_sizes[k]) {
            case 16777216: x  = (const float*)d_in[k]; break;
            case 6144:     W1 = (const float*)d_in[k]; break;
            case 128:      b1 = (const float*)d_in[k]; break;
            case 2048:     W2 = (const float*)d_in[k]; break;
            case 16:       b2 = (const float*)d_in[k]; break;
            case 1048576:  ru = (const float*)d_in[k]; break;
            default: break;
        }
    }
    float* out = (float*)d_out;

    cudaFuncSetAttribute(nca_pass1, cudaFuncAttributeMaxDynamicSharedMemorySize, SMEM_BYTES);
    nca_prep<<<24, 256>>>(W1, W2);
    nca_pass1<<<8192, 256, SMEM_BYTES>>>(x, b1, b2, ru, out);
    nca_pass2<<<4096, 256>>>(out);
}

// round 9
// speedup vs baseline: 2.0388x; 1.1180x over previous
#include <cuda_runtime.h>
#include <cuda_fp16.h>
#include <cstdint>

#define BATCH 16
#define HH 256
#define WW 256
#define NPIX (BATCH*HH*WW)

// ---- scratch (__device__ globals; no allocs allowed) ----
__device__ float g_aold[NPIX];                // 4MB
__device__ float g_anew[NPIX];                // 4MB
__device__ __align__(16) unsigned char g_B1[128 * 104 * 2];  // f16 [128n][104k] (hi 0:48 | lo 48:96)
__device__ __align__(16) unsigned char g_B2[16 * 264 * 2];   // f16 [16n][264k] (hi 0:128 | lo 128:256)

// ================= warp-MMA helpers =================
__device__ __forceinline__ uint32_t smem_u32(const void* p) {
    uint32_t a;
    asm("{ .reg .u64 t; cvta.to.shared.u64 t, %1; cvt.u32.u64 %0, t; }" : "=r"(a) : "l"(p));
    return a;
}
__device__ __forceinline__ void ldsm4(uint32_t* r, uint32_t addr) {
    asm volatile("ldmatrix.sync.aligned.m8n8.x4.shared.b16 {%0,%1,%2,%3}, [%4];"
        : "=r"(r[0]), "=r"(r[1]), "=r"(r[2]), "=r"(r[3]) : "r"(addr));
}
__device__ __forceinline__ void mma_f16(float* d, const uint32_t* a, uint32_t b0, uint32_t b1) {
    asm volatile("mma.sync.aligned.m16n8k16.row.col.f32.f16.f16.f32 "
        "{%0,%1,%2,%3}, {%4,%5,%6,%7}, {%8,%9}, {%0,%1,%2,%3};"
        : "+f"(d[0]), "+f"(d[1]), "+f"(d[2]), "+f"(d[3])
        : "r"(a[0]), "r"(a[1]), "r"(a[2]), "r"(a[3]), "r"(b0), "r"(b1));
}
__device__ __forceinline__ uint16_t f16_bits(float f) {
    return __half_as_ushort(__float2half(f));
}
__device__ __forceinline__ float f16_val(uint16_t u) {
    return __half2float(__ushort_as_half(u));
}
__device__ __forceinline__ uint32_t pack2(float a, float b) {
    return (uint32_t)f16_bits(a) | ((uint32_t)f16_bits(b) << 16);
}

// ================= prep: f16 hi/lo weight tile images ==========
__global__ void nca_prep(const float* __restrict__ W1, const float* __restrict__ W2)
{
    int q = blockIdx.x * 256 + threadIdx.x;    // 24 x 256
    __half* B1 = (__half*)g_B1;
    __half* B2 = (__half*)g_B2;
    if (q < 6144) {                            // W1 [48k][128n]
        int k = q >> 7, n = q & 127;
        float v = W1[q];
        __half h = __float2half(v);
        B1[n * 104 + k]      = h;
        B1[n * 104 + 48 + k] = __float2half(v - __half2float(h));
    }
    if (q < 2048) {                            // W2 [128d][16c]
        int d = q >> 4, c = q & 15;
        float v = W2[q];
        __half h = __float2half(v);
        B2[c * 264 + d]       = h;
        B2[c * 264 + 128 + d] = __float2half(v - __half2float(h));
    }
}

// ================= Pass 1 ===================================================
// CTA = 128 pixels, 512 threads / 16 warps. Warp (pg, h): pg = t>>6 pixel
// group [16pg,16pg+16), h = n-half (64 hid dims). GEMM1 fp16 2-term
// (Ahi*Bhi + Alo*Bhi); GEMM2 fp16 3-term (Hhi*Whi + Hlo*Whi + Hhi*Wlo),
// partial-K per warp + SMEM pair-reduction.
//
// SMEM (bytes):
//   A1  @ 0      : f16 [128 px][104] = 26624   (reduction buf 16KB after GEMM1)
//   B1  @ 26624  : f16 [128 n][104]  = 26624
//   B2  @ 53248  : f16 [16 n][264]   = 8448
//   XH  @ 61696  : f32 [3][132][20] pixel-major = 31680
//   b1v @ 93376  : f32[128]; b2v @ 93888 : f32[16]
#define SM_A1   0
#define SM_RED  0
#define SM_B1   26624
#define SM_B2   53248
#define SM_XH   61696
#define SM_B1V  93376
#define SM_B2V  93888
#define SMEM_BYTES 93952

#define XH_F(rr, cc, c) (((rr) * 132 + (cc)) * 20 + (c))

extern __shared__ unsigned char sm[];

__global__ void __launch_bounds__(512, 2) nca_pass1(
    const float* __restrict__ x,  const float* __restrict__ b1,
    const float* __restrict__ b2, const float* __restrict__ ru,
    float* __restrict__ out)
{
    const uint32_t smb = smem_u32(sm);
    float* XH = (float*)(sm + SM_XH);

    const int t    = threadIdx.x;
    const int w16  = t >> 5;            // warp 0..15
    const int lane = t & 31;
    const int pg   = w16 >> 1;          // pixel group 0..7
    const int h    = w16 & 1;           // n-half 0..1
    const int bid  = blockIdx.x;
    const int tile = bid & 1;
    const int row  = bid >> 1;
    const int b    = row >> 8;
    const int i    = row & 255;
    const int j0   = tile << 7;

    // ---- cooperative tile copies (L2-hot) + bias loads ----
    for (int q = t; q < 1664; q += 512)
        ((float4*)(sm + SM_B1))[q] = ((const float4*)g_B1)[q];
    for (int q = t; q < 528; q += 512)
        ((float4*)(sm + SM_B2))[q] = ((const float4*)g_B2)[q];
    if (t < 128) ((float*)(sm + SM_B1V))[t] = b1[t];
    if (t < 16)  ((float*)(sm + SM_B2V))[t] = b2[t];

    // ---- x-halo: 3 rows x 130 cols x 16 ch -> pixel-major XH ----
    for (int task = t; task < 1560; task += 512) {
        int rr  = task / 520;
        int rem = task - rr * 520;
        int cc  = rem >> 2;
        int cg  = rem & 3;
        int gi  = i + rr - 1;
        int jc  = j0 + cc - 1;
        float4 v = make_float4(0.f, 0.f, 0.f, 0.f);
        if (gi >= 0 && gi < HH && jc >= 0 && jc < WW)
            v = *(const float4*)(x + (((size_t)(b * HH + gi) * WW + jc) << 4) + (cg << 2));
        *(float4*)(XH + XH_F(rr, cc, cg * 4)) = v;
    }
    __syncthreads();

    // ---- perceive: thread = (pixel pp, channel-quad g). 9 LDS.128 in,
    //      12 hi + 12 lo f16 out (uint4+uint2 stores) ----
    {
        const int pp = t & 127;
        const int g  = t >> 7;           // 0..3, channels 4g..4g+3
        float4 v[3][3];
        #pragma unroll
        for (int rr = 0; rr < 3; rr++)
            #pragma unroll
            for (int cx = 0; cx < 3; cx++)
                v[rr][cx] = *(const float4*)(XH + XH_F(rr, pp + cx, 4 * g));

        uint32_t hi[6], lo[6];
        #pragma unroll
        for (int cq = 0; cq < 4; cq++) {
            float a00 = ((const float*)&v[0][0])[cq];
            float a01 = ((const float*)&v[0][1])[cq];
            float a02 = ((const float*)&v[0][2])[cq];
            float a10 = ((const float*)&v[1][0])[cq];
            float a11 = ((const float*)&v[1][1])[cq];
            float a12 = ((const float*)&v[1][2])[cq];
            float a20 = ((const float*)&v[2][0])[cq];
            float a21 = ((const float*)&v[2][1])[cq];
            float a22 = ((const float*)&v[2][2])[cq];
            float yv[3];
            yv[0] = a11;
            yv[1] = ((a02 + 2.f * a12 + a22) - (a00 + 2.f * a10 + a20)) * 0.125f;
            yv[2] = ((a20 + 2.f * a21 + a22) - (a00 + 2.f * a01 + a02)) * 0.125f;
            #pragma unroll
            for (int e2 = 0; e2 < 3; e2++) {
                int m = 3 * cq + e2;      // 0..11
                uint16_t hb = f16_bits(yv[e2]);
                uint16_t lb = f16_bits(yv[e2] - f16_val(hb));
                if (m & 1) { hi[m >> 1] |= (uint32_t)hb << 16; lo[m >> 1] |= (uint32_t)lb << 16; }
                else       { hi[m >> 1]  = (uint32_t)hb;       lo[m >> 1]  = (uint32_t)lb; }
            }
        }
        unsigned char* rowp = sm + SM_A1 + pp * 208;
        const int off = 24 * g;           // k byte offset: 12 k-vals = 24B
        if (g & 1) {
            *(uint2*)(rowp + off)          = make_uint2(hi[0], hi[1]);
            *(uint4*)(rowp + off + 8)      = make_uint4(hi[2], hi[3], hi[4], hi[5]);
            *(uint2*)(rowp + 96 + off)     = make_uint2(lo[0], lo[1]);
            *(uint4*)(rowp + 96 + off + 8) = make_uint4(lo[2], lo[3], lo[4], lo[5]);
        } else {
            *(uint4*)(rowp + off)           = make_uint4(hi[0], hi[1], hi[2], hi[3]);
            *(uint2*)(rowp + off + 16)      = make_uint2(hi[4], hi[5]);
            *(uint4*)(rowp + 96 + off)      = make_uint4(lo[0], lo[1], lo[2], lo[3]);
            *(uint2*)(rowp + 96 + off + 16) = make_uint2(lo[4], lo[5]);
        }
    }
    __syncthreads();

    // ---- prefetch ru for epilogue pixels ----
    const int c0 = (lane & 3) * 2;
    const int p0 = 16 * pg + (lane >> 2);
    const size_t pixbase = (size_t)(b * HH + i) * WW + j0;
    float u0 = 0.f, u1 = 0.f;
    if (h == 0) { u0 = ru[pixbase + p0]; u1 = ru[pixbase + p0 + 8]; }

    // ---- GEMM1: acc[8 n8-tiles][4] = A1[16pg..][48] x B1hi[64h..] (2 terms) --
    float acc[8][4];
    #pragma unroll
    for (int j = 0; j < 8; j++)
        #pragma unroll
        for (int r = 0; r < 4; r++) acc[j][r] = 0.f;

    {
        uint32_t ah[3][4], al[3][4];
        const uint32_t aBase = smb + SM_A1 + (16 * pg + (lane & 15)) * 208 + (lane >> 4) * 16;
        #pragma unroll
        for (int ks = 0; ks < 3; ks++) {
            ldsm4(ah[ks], aBase + ks * 32);
            ldsm4(al[ks], aBase + 96 + ks * 32);
        }
        const uint32_t bBase = smb + SM_B1
            + (64 * h + (lane & 7) + ((lane >> 4) & 1) * 8) * 208 + ((lane >> 3) & 1) * 16;
        #pragma unroll
        for (int jj = 0; jj < 4; jj++) {
            #pragma unroll
            for (int ks = 0; ks < 3; ks++) {
                uint32_t bh[4];
                ldsm4(bh, bBase + jj * (16 * 208) + ks * 32);
                mma_f16(acc[2 * jj],     ah[ks], bh[0], bh[1]);
                mma_f16(acc[2 * jj + 1], ah[ks], bh[2], bh[3]);
                mma_f16(acc[2 * jj],     al[ks], bh[0], bh[1]);
                mma_f16(acc[2 * jj + 1], al[ks], bh[2], bh[3]);
            }
        }
    }

    // ---- GEMM2 partial-K (register-fed, 3 terms): this warp's h-dims are
    //      K = [64h, 64h+64) of the 128-dim hidden ----
    float acc2[2][4];
    #pragma unroll
    for (int j = 0; j < 2; j++)
        #pragma unroll
        for (int r = 0; r < 4; r++) acc2[j][r] = 0.f;

    {
        const float* b1s = (const float*)(sm + SM_B1V);
        const uint32_t b2Base = smb + SM_B2 + ((lane & 7) + ((lane >> 4) & 1) * 8) * 528
                                            + ((lane >> 3) & 1) * 16;
        #pragma unroll
        for (int jj = 0; jj < 4; jj++) {
            int kk = 4 * h + jj;                 // K16-chunk index in [0,8)
            int n0 = 64 * h + 16 * jj + c0;
            int n1 = n0 + 8;
            float bn00 = b1s[n0], bn01 = b1s[n0 + 1];
            float bn10 = b1s[n1], bn11 = b1s[n1 + 1];
            float v00 = fmaxf(acc[2 * jj][0] + bn00, 0.f);
            float v01 = fmaxf(acc[2 * jj][1] + bn01, 0.f);
            float v02 = fmaxf(acc[2 * jj][2] + bn00, 0.f);
            float v03 = fmaxf(acc[2 * jj][3] + bn01, 0.f);
            float v10 = fmaxf(acc[2 * jj + 1][0] + bn10, 0.f);
            float v11 = fmaxf(acc[2 * jj + 1][1] + bn11, 0.f);
            float v12 = fmaxf(acc[2 * jj + 1][2] + bn10, 0.f);
            float v13 = fmaxf(acc[2 * jj + 1][3] + bn11, 0.f);
            uint32_t ahi[4], alo[4];
            ahi[0] = pack2(v00, v01);
            ahi[1] = pack2(v02, v03);
            ahi[2] = pack2(v10, v11);
            ahi[3] = pack2(v12, v13);
            alo[0] = pack2(v00 - f16_val((uint16_t)ahi[0]), v01 - f16_val((uint16_t)(ahi[0] >> 16)));
            alo[1] = pack2(v02 - f16_val((uint16_t)ahi[1]), v03 - f16_val((uint16_t)(ahi[1] >> 16)));
            alo[2] = pack2(v10 - f16_val((uint16_t)ahi[2]), v11 - f16_val((uint16_t)(ahi[2] >> 16)));
            alo[3] = pack2(v12 - f16_val((uint16_t)ahi[3]), v13 - f16_val((uint16_t)(ahi[3] >> 16)));

            uint32_t bh[4], bl[4];
            ldsm4(bh, b2Base + kk * 32);
            ldsm4(bl, b2Base + 256 + kk * 32);   // W2lo at k=128 -> +256B
            mma_f16(acc2[0], ahi, bh[0], bh[1]);
            mma_f16(acc2[1], ahi, bh[2], bh[3]);
            mma_f16(acc2[0], alo, bh[0], bh[1]);
            mma_f16(acc2[1], alo, bh[2], bh[3]);
            mma_f16(acc2[0], ahi, bl[0], bl[1]);
            mma_f16(acc2[1], ahi, bl[2], bl[3]);
        }
    }

    // ---- cross-warp K-reduction: (pg,0) += (pg,1), via SMEM over dead A1 ----
    __syncthreads();                     // all A1/B1 reads complete
    {
        float4* red = (float4*)(sm + SM_RED);
        int idx = (w16 * 32 + lane) * 2;
        red[idx]     = make_float4(acc2[0][0], acc2[0][1], acc2[0][2], acc2[0][3]);
        red[idx + 1] = make_float4(acc2[1][0], acc2[1][1], acc2[1][2], acc2[1][3]);
    }
    __syncthreads();

    // ---- epilogue (h==0 warps): dx + stochastic update -> out + alpha ----
    if (h == 0) {
        const float4* red = (const float4*)(sm + SM_RED);
        int pidx = ((w16 + 1) * 32 + lane) * 2;
        float4 pa = red[pidx], pb = red[pidx + 1];
        acc2[0][0] += pa.x; acc2[0][1] += pa.y; acc2[0][2] += pa.z; acc2[0][3] += pa.w;
        acc2[1][0] += pb.x; acc2[1][1] += pb.y; acc2[1][2] += pb.z; acc2[1][3] += pb.w;

        const float* b2s = (const float*)(sm + SM_B2V);
        float bc0 = b2s[c0], bc1 = b2s[c0 + 1], bc8 = b2s[c0 + 8], bc9 = b2s[c0 + 9];
        #pragma unroll
        for (int px = 0; px < 2; px++) {
            int p = p0 + px * 8;
            const float* xo = XH + XH_F(1, p + 1, 0);
            float xo0 = xo[c0],     xo1 = xo[c0 + 1];
            float xo2 = xo[c0 + 8], xo3 = xo[c0 + 9];
            size_t pix = pixbase + p;
            float um = ((px ? u1 : u0) <= 0.5f) ? 1.f : 0.f;
            float xn0 = xo0 + (acc2[0][2 * px]     + bc0) * um;
            float xn1 = xo1 + (acc2[0][2 * px + 1] + bc1) * um;
            float xn2 = xo2 + (acc2[1][2 * px]     + bc8) * um;
            float xn3 = xo3 + (acc2[1][2 * px + 1] + bc9) * um;
            *(float2*)(out + pix * 16 + c0)     = make_float2(xn0, xn1);
            *(float2*)(out + pix * 16 + c0 + 8) = make_float2(xn2, xn3);
            if ((lane & 3) == 1) {               // c0==2 -> channel 3 = slot 1
                g_aold[pix] = xo1;
                g_anew[pix] = xn1;
            }
        }
    }
}

// ================= Pass 2: zero the dead pixels only =========================
__global__ void __launch_bounds__(256) nca_pass2(float* __restrict__ out)
{
    __shared__ float sao[3][256];
    __shared__ float san[3][256];
    const int t   = threadIdx.x;
    const int row = blockIdx.x;
    const int b   = row >> 8;
    const int i   = row & 255;

    #pragma unroll
    for (int rr = 0; rr < 3; rr++) {
        int gi = i + rr - 1;
        float vo = -1e30f, vn = -1e30f;
        if (gi >= 0 && gi < HH) {
            size_t idx = (size_t)(b * HH + gi) * WW + t;
            vo = g_aold[idx];
            vn = g_anew[idx];
        }
        sao[rr][t] = vo;
        san[rr][t] = vn;
    }
    __syncthreads();

    float mo = -1e30f, mn = -1e30f;
    #pragma unroll
    for (int rr = 0; rr < 3; rr++) {
        #pragma unroll
        for (int dc = 0; dc < 3; dc++) {
            int jc = t + dc - 1;
            if (jc >= 0 && jc < WW) {
                mo = fmaxf(mo, sao[rr][jc]);
                mn = fmaxf(mn, san[rr][jc]);
            }
        }
    }
    if (!(mo > 0.1f && mn > 0.1f)) {
        size_t pix = (size_t)row * WW + t;
        float4 z = make_float4(0.f, 0.f, 0.f, 0.f);
        float4* dst = (float4*)(out + pix * 16);
        dst[0] = z; dst[1] = z; dst[2] = z; dst[3] = z;
    }
}

extern "C" void kernel_launch(void* const* d_in, const int* in_sizes, int n_in,
                              void* d_out, int out_size)
{
    const float *x = nullptr, *W1 = nullptr, *b1 = nullptr,
                *W2 = nullptr, *b2 = nullptr, *ru = nullptr;
    for (int k = 0; k < n_in; k++) {
        switch (in_sizes[k]) {
            case 16777216: x  = (const float*)d_in[k]; break;
            case 6144:     W1 = (const float*)d_in[k]; break;
            case 128:      b1 = (const float*)d_in[k]; break;
            case 2048:     W2 = (const float*)d_in[k]; break;
            case 16:       b2 = (const float*)d_in[k]; break;
            case 1048576:  ru = (const float*)d_in[k]; break;
            default: break;
        }
    }
    float* out = (float*)d_out;

    cudaFuncSetAttribute(nca_pass1, cudaFuncAttributeMaxDynamicSharedMemorySize, SMEM_BYTES);
    nca_prep<<<24, 256>>>(W1, W2);
    nca_pass1<<<8192, 512, SMEM_BYTES>>>(x, b1, b2, ru, out);
    nca_pass2<<<4096, 256>>>(out);
}

// round 10
// speedup vs baseline: 2.3556x; 1.1554x over previous
#include <cuda_runtime.h>
#include <cuda_fp16.h>
#include <cstdint>

#define BATCH 16
#define HH 256
#define WW 256
#define NPIX (BATCH*HH*WW)

// ---- scratch (__device__ globals; no allocs allowed) ----
__device__ float g_aold[NPIX];                // 4MB
__device__ float g_anew[NPIX];                // 4MB
__device__ __align__(16) unsigned char g_B1[128 * 104 * 2];  // f16 [128n][104k] (hi 0:48 | lo 48:96)
__device__ __align__(16) unsigned char g_B2[16 * 264 * 2];   // f16 [16n][264k] (hi 0:128 | lo 128:256)

// ================= warp-MMA / async-copy helpers =================
__device__ __forceinline__ uint32_t smem_u32(const void* p) {
    uint32_t a;
    asm("{ .reg .u64 t; cvta.to.shared.u64 t, %1; cvt.u32.u64 %0, t; }" : "=r"(a) : "l"(p));
    return a;
}
__device__ __forceinline__ void ldsm4(uint32_t* r, uint32_t addr) {
    asm volatile("ldmatrix.sync.aligned.m8n8.x4.shared.b16 {%0,%1,%2,%3}, [%4];"
        : "=r"(r[0]), "=r"(r[1]), "=r"(r[2]), "=r"(r[3]) : "r"(addr));
}
__device__ __forceinline__ void mma_f16(float* d, const uint32_t* a, uint32_t b0, uint32_t b1) {
    asm volatile("mma.sync.aligned.m16n8k16.row.col.f32.f16.f16.f32 "
        "{%0,%1,%2,%3}, {%4,%5,%6,%7}, {%8,%9}, {%0,%1,%2,%3};"
        : "+f"(d[0]), "+f"(d[1]), "+f"(d[2]), "+f"(d[3])
        : "r"(a[0]), "r"(a[1]), "r"(a[2]), "r"(a[3]), "r"(b0), "r"(b1));
}
__device__ __forceinline__ void cp16(uint32_t dst, const void* src) {
    asm volatile("cp.async.cg.shared.global [%0], [%1], 16;" :: "r"(dst), "l"(src));
}
__device__ __forceinline__ void cp16z(uint32_t dst, const void* src, bool pred) {
    int sz = pred ? 16 : 0;       // src_size=0 -> zero-fill (CUTLASS zfill pattern)
    asm volatile("cp.async.cg.shared.global [%0], [%1], 16, %2;"
                 :: "r"(dst), "l"(src), "r"(sz));
}
__device__ __forceinline__ void cp_wait_all() {
    asm volatile("cp.async.commit_group;");
    asm volatile("cp.async.wait_group 0;");
}
__device__ __forceinline__ uint16_t f16_bits(float f) {
    return __half_as_ushort(__float2half(f));
}
__device__ __forceinline__ float f16_val(uint16_t u) {
    return __half2float(__ushort_as_half(u));
}
__device__ __forceinline__ uint32_t pack2(float a, float b) {
    return (uint32_t)f16_bits(a) | ((uint32_t)f16_bits(b) << 16);
}

// ================= prep: f16 hi/lo weight tile images ==========
__global__ void nca_prep(const float* __restrict__ W1, const float* __restrict__ W2)
{
    int q = blockIdx.x * 256 + threadIdx.x;    // 24 x 256
    __half* B1 = (__half*)g_B1;
    __half* B2 = (__half*)g_B2;
    if (q < 6144) {                            // W1 [48k][128n]
        int k = q >> 7, n = q & 127;
        float v = W1[q];
        __half h = __float2half(v);
        B1[n * 104 + k]      = h;
        B1[n * 104 + 48 + k] = __float2half(v - __half2float(h));
    }
    if (q < 2048) {                            // W2 [128d][16c]
        int d = q >> 4, c = q & 15;
        float v = W2[q];
        __half h = __float2half(v);
        B2[c * 264 + d]       = h;
        B2[c * 264 + 128 + d] = __float2half(v - __half2float(h));
    }
}

// ================= Pass 1 ===================================================
// CTA = 128 pixels, 512 threads / 16 warps. Warp (pg, h): pg pixel group,
// h n-half. GEMM1 fp16 2-term; GEMM2 fp16 3-term partial-K + SMEM reduction.
// Front phase (weights + halo) via cp.async (zero-fill OOB).
//
// SMEM (bytes):
//   A1  @ 0      : f16 [128 px][104] = 26624   (reduction buf after GEMM1)
//   B1  @ 26624  : f16 [128 n][104]  = 26624
//   B2  @ 53248  : f16 [16 n][264]   = 8448
//   XH  @ 61696  : f32 [3][132][20] pixel-major = 31680
//   b1v @ 93376  : f32[128]; b2v @ 93888 : f32[16]
#define SM_A1   0
#define SM_RED  0
#define SM_B1   26624
#define SM_B2   53248
#define SM_XH   61696
#define SM_B1V  93376
#define SM_B2V  93888
#define SMEM_BYTES 93952

#define XH_F(rr, cc, c) (((rr) * 132 + (cc)) * 20 + (c))

extern __shared__ unsigned char sm[];

__global__ void __launch_bounds__(512, 2) nca_pass1(
    const float* __restrict__ x,  const float* __restrict__ b1,
    const float* __restrict__ b2, const float* __restrict__ ru,
    float* __restrict__ out)
{
    const uint32_t smb = smem_u32(sm);
    float* XH = (float*)(sm + SM_XH);

    const int t    = threadIdx.x;
    const int w16  = t >> 5;
    const int lane = t & 31;
    const int pg   = w16 >> 1;
    const int h    = w16 & 1;
    const int bid  = blockIdx.x;
    const int tile = bid & 1;
    const int row  = bid >> 1;
    const int b    = row >> 8;
    const int i    = row & 255;
    const int j0   = tile << 7;

    // ---- front phase: all bulk loads via cp.async ----
    for (int q = t; q < 1664; q += 512)
        cp16(smb + SM_B1 + q * 16, (const char*)g_B1 + q * 16);
    for (int q = t; q < 528; q += 512)
        cp16(smb + SM_B2 + q * 16, (const char*)g_B2 + q * 16);

    // x-halo: 3 rows x 130 cols x 16 ch -> pixel-major XH (zero-fill OOB)
    for (int task = t; task < 1560; task += 512) {
        int rr  = task / 520;
        int rem = task - rr * 520;
        int cc  = rem >> 2;
        int cg  = rem & 3;
        int gi  = i + rr - 1;
        int jc  = j0 + cc - 1;
        bool ok = (gi >= 0 && gi < HH && jc >= 0 && jc < WW);
        const float* src = x + ((((size_t)(b * HH + (ok ? gi : 0)) * WW + (ok ? jc : 0))) << 4)
                             + (cg << 2);
        cp16z(smb + SM_XH + XH_F(rr, cc, cg * 4) * 4, src, ok);
    }
    if (t < 128) ((float*)(sm + SM_B1V))[t] = b1[t];
    if (t < 16)  ((float*)(sm + SM_B2V))[t] = b2[t];
    cp_wait_all();
    __syncthreads();

    // ---- perceive: thread = (pixel pp, channel-quad g); 9 LDS.128 in ----
    {
        const int pp = t & 127;
        const int g  = t >> 7;           // 0..3, channels 4g..4g+3
        float4 v[3][3];
        #pragma unroll
        for (int rr = 0; rr < 3; rr++)
            #pragma unroll
            for (int cx = 0; cx < 3; cx++)
                v[rr][cx] = *(const float4*)(XH + XH_F(rr, pp + cx, 4 * g));

        uint32_t hi[6], lo[6];
        #pragma unroll
        for (int cq = 0; cq < 4; cq++) {
            float a00 = ((const float*)&v[0][0])[cq];
            float a01 = ((const float*)&v[0][1])[cq];
            float a02 = ((const float*)&v[0][2])[cq];
            float a10 = ((const float*)&v[1][0])[cq];
            float a11 = ((const float*)&v[1][1])[cq];
            float a12 = ((const float*)&v[1][2])[cq];
            float a20 = ((const float*)&v[2][0])[cq];
            float a21 = ((const float*)&v[2][1])[cq];
            float a22 = ((const float*)&v[2][2])[cq];
            float yv[3];
            yv[0] = a11;
            yv[1] = ((a02 + 2.f * a12 + a22) - (a00 + 2.f * a10 + a20)) * 0.125f;
            yv[2] = ((a20 + 2.f * a21 + a22) - (a00 + 2.f * a01 + a02)) * 0.125f;
            #pragma unroll
            for (int e2 = 0; e2 < 3; e2++) {
                int m = 3 * cq + e2;
                uint16_t hb = f16_bits(yv[e2]);
                uint16_t lb = f16_bits(yv[e2] - f16_val(hb));
                if (m & 1) { hi[m >> 1] |= (uint32_t)hb << 16; lo[m >> 1] |= (uint32_t)lb << 16; }
                else       { hi[m >> 1]  = (uint32_t)hb;       lo[m >> 1]  = (uint32_t)lb; }
            }
        }
        unsigned char* rowp = sm + SM_A1 + pp * 208;
        const int off = 24 * g;
        if (g & 1) {
            *(uint2*)(rowp + off)          = make_uint2(hi[0], hi[1]);
            *(uint4*)(rowp + off + 8)      = make_uint4(hi[2], hi[3], hi[4], hi[5]);
            *(uint2*)(rowp + 96 + off)     = make_uint2(lo[0], lo[1]);
            *(uint4*)(rowp + 96 + off + 8) = make_uint4(lo[2], lo[3], lo[4], lo[5]);
        } else {
            *(uint4*)(rowp + off)           = make_uint4(hi[0], hi[1], hi[2], hi[3]);
            *(uint2*)(rowp + off + 16)      = make_uint2(hi[4], hi[5]);
            *(uint4*)(rowp + 96 + off)      = make_uint4(lo[0], lo[1], lo[2], lo[3]);
            *(uint2*)(rowp + 96 + off + 16) = make_uint2(lo[4], lo[5]);
        }
    }
    __syncthreads();

    // ---- prefetch ru for epilogue pixels ----
    const int c0 = (lane & 3) * 2;
    const int p0 = 16 * pg + (lane >> 2);
    const size_t pixbase = (size_t)(b * HH + i) * WW + j0;
    float u0 = 0.f, u1 = 0.f;
    if (h == 0) { u0 = ru[pixbase + p0]; u1 = ru[pixbase + p0 + 8]; }

    // ---- GEMM1: acc[8 n8-tiles][4] = A1[16pg..][48] x B1hi[64h..] (2 terms) --
    float acc[8][4];
    #pragma unroll
    for (int j = 0; j < 8; j++)
        #pragma unroll
        for (int r = 0; r < 4; r++) acc[j][r] = 0.f;

    {
        uint32_t ah[3][4], al[3][4];
        const uint32_t aBase = smb + SM_A1 + (16 * pg + (lane & 15)) * 208 + (lane >> 4) * 16;
        #pragma unroll
        for (int ks = 0; ks < 3; ks++) {
            ldsm4(ah[ks], aBase + ks * 32);
            ldsm4(al[ks], aBase + 96 + ks * 32);
        }
        const uint32_t bBase = smb + SM_B1
            + (64 * h + (lane & 7) + ((lane >> 4) & 1) * 8) * 208 + ((lane >> 3) & 1) * 16;
        #pragma unroll
        for (int jj = 0; jj < 4; jj++) {
            #pragma unroll
            for (int ks = 0; ks < 3; ks++) {
                uint32_t bh[4];
                ldsm4(bh, bBase + jj * (16 * 208) + ks * 32);
                mma_f16(acc[2 * jj],     ah[ks], bh[0], bh[1]);
                mma_f16(acc[2 * jj + 1], ah[ks], bh[2], bh[3]);
                mma_f16(acc[2 * jj],     al[ks], bh[0], bh[1]);
                mma_f16(acc[2 * jj + 1], al[ks], bh[2], bh[3]);
            }
        }
    }

    // ---- GEMM2 partial-K (register-fed, 3 terms) ----
    float acc2[2][4];
    #pragma unroll
    for (int j = 0; j < 2; j++)
        #pragma unroll
        for (int r = 0; r < 4; r++) acc2[j][r] = 0.f;

    {
        const float* b1s = (const float*)(sm + SM_B1V);
        const uint32_t b2Base = smb + SM_B2 + ((lane & 7) + ((lane >> 4) & 1) * 8) * 528
                                            + ((lane >> 3) & 1) * 16;
        #pragma unroll
        for (int jj = 0; jj < 4; jj++) {
            int kk = 4 * h + jj;
            int n0 = 64 * h + 16 * jj + c0;
            int n1 = n0 + 8;
            float bn00 = b1s[n0], bn01 = b1s[n0 + 1];
            float bn10 = b1s[n1], bn11 = b1s[n1 + 1];
            float v00 = fmaxf(acc[2 * jj][0] + bn00, 0.f);
            float v01 = fmaxf(acc[2 * jj][1] + bn01, 0.f);
            float v02 = fmaxf(acc[2 * jj][2] + bn00, 0.f);
            float v03 = fmaxf(acc[2 * jj][3] + bn01, 0.f);
            float v10 = fmaxf(acc[2 * jj + 1][0] + bn10, 0.f);
            float v11 = fmaxf(acc[2 * jj + 1][1] + bn11, 0.f);
            float v12 = fmaxf(acc[2 * jj + 1][2] + bn10, 0.f);
            float v13 = fmaxf(acc[2 * jj + 1][3] + bn11, 0.f);
            uint32_t ahi[4], alo[4];
            ahi[0] = pack2(v00, v01);
            ahi[1] = pack2(v02, v03);
            ahi[2] = pack2(v10, v11);
            ahi[3] = pack2(v12, v13);
            alo[0] = pack2(v00 - f16_val((uint16_t)ahi[0]), v01 - f16_val((uint16_t)(ahi[0] >> 16)));
            alo[1] = pack2(v02 - f16_val((uint16_t)ahi[1]), v03 - f16_val((uint16_t)(ahi[1] >> 16)));
            alo[2] = pack2(v10 - f16_val((uint16_t)ahi[2]), v11 - f16_val((uint16_t)(ahi[2] >> 16)));
            alo[3] = pack2(v12 - f16_val((uint16_t)ahi[3]), v13 - f16_val((uint16_t)(ahi[3] >> 16)));

            uint32_t bh[4], bl[4];
            ldsm4(bh, b2Base + kk * 32);
            ldsm4(bl, b2Base + 256 + kk * 32);
            mma_f16(acc2[0], ahi, bh[0], bh[1]);
            mma_f16(acc2[1], ahi, bh[2], bh[3]);
            mma_f16(acc2[0], alo, bh[0], bh[1]);
            mma_f16(acc2[1], alo, bh[2], bh[3]);
            mma_f16(acc2[0], ahi, bl[0], bl[1]);
            mma_f16(acc2[1], ahi, bl[2], bl[3]);
        }
    }

    // ---- cross-warp K-reduction via SMEM over dead A1 ----
    __syncthreads();
    {
        float4* red = (float4*)(sm + SM_RED);
        int idx = (w16 * 32 + lane) * 2;
        red[idx]     = make_float4(acc2[0][0], acc2[0][1], acc2[0][2], acc2[0][3]);
        red[idx + 1] = make_float4(acc2[1][0], acc2[1][1], acc2[1][2], acc2[1][3]);
    }
    __syncthreads();

    // ---- epilogue (h==0 warps) ----
    if (h == 0) {
        const float4* red = (const float4*)(sm + SM_RED);
        int pidx = ((w16 + 1) * 32 + lane) * 2;
        float4 pa = red[pidx], pb = red[pidx + 1];
        acc2[0][0] += pa.x; acc2[0][1] += pa.y; acc2[0][2] += pa.z; acc2[0][3] += pa.w;
        acc2[1][0] += pb.x; acc2[1][1] += pb.y; acc2[1][2] += pb.z; acc2[1][3] += pb.w;

        const float* b2s = (const float*)(sm + SM_B2V);
        float bc0 = b2s[c0], bc1 = b2s[c0 + 1], bc8 = b2s[c0 + 8], bc9 = b2s[c0 + 9];
        #pragma unroll
        for (int px = 0; px < 2; px++) {
            int p = p0 + px * 8;
            const float* xo = XH + XH_F(1, p + 1, 0);
            float xo0 = xo[c0],     xo1 = xo[c0 + 1];
            float xo2 = xo[c0 + 8], xo3 = xo[c0 + 9];
            size_t pix = pixbase + p;
            float um = ((px ? u1 : u0) <= 0.5f) ? 1.f : 0.f;
            float xn0 = xo0 + (acc2[0][2 * px]     + bc0) * um;
            float xn1 = xo1 + (acc2[0][2 * px + 1] + bc1) * um;
            float xn2 = xo2 + (acc2[1][2 * px]     + bc8) * um;
            float xn3 = xo3 + (acc2[1][2 * px + 1] + bc9) * um;
            *(float2*)(out + pix * 16 + c0)     = make_float2(xn0, xn1);
            *(float2*)(out + pix * 16 + c0 + 8) = make_float2(xn2, xn3);
            if ((lane & 3) == 1) {
                g_aold[pix] = xo1;
                g_anew[pix] = xn1;
            }
        }
    }
}

// ================= Pass 2: zero the dead pixels only =========================
__global__ void __launch_bounds__(256) nca_pass2(float* __restrict__ out)
{
    __shared__ float sao[3][256];
    __shared__ float san[3][256];
    const int t   = threadIdx.x;
    const int row = blockIdx.x;
    const int b   = row >> 8;
    const int i   = row & 255;

    #pragma unroll
    for (int rr = 0; rr < 3; rr++) {
        int gi = i + rr - 1;
        float vo = -1e30f, vn = -1e30f;
        if (gi >= 0 && gi < HH) {
            size_t idx = (size_t)(b * HH + gi) * WW + t;
            vo = g_aold[idx];
            vn = g_anew[idx];
        }
        sao[rr][t] = vo;
        san[rr][t] = vn;
    }
    __syncthreads();

    float mo = -1e30f, mn = -1e30f;
    #pragma unroll
    for (int rr = 0; rr < 3; rr++) {
        #pragma unroll
        for (int dc = 0; dc < 3; dc++) {
            int jc = t + dc - 1;
            if (jc >= 0 && jc < WW) {
                mo = fmaxf(mo, sao[rr][jc]);
                mn = fmaxf(mn, san[rr][jc]);
            }
        }
    }
    if (!(mo > 0.1f && mn > 0.1f)) {
        size_t pix = (size_t)row * WW + t;
        float4 z = make_float4(0.f, 0.f, 0.f, 0.f);
        float4* dst = (float4*)(out + pix * 16);
        dst[0] = z; dst[1] = z; dst[2] = z; dst[3] = z;
    }
}

// 4th launch per replay: shifts the ncu skip-window off nca_prep so the
// next profile captures nca_pass1. Touches one scratch word (kept deterministic).
__global__ void nca_probe() {
    if (threadIdx.x == 0) g_aold[0] = g_aold[0];
}

extern "C" void kernel_launch(void* const* d_in, const int* in_sizes, int n_in,
                              void* d_out, int out_size)
{
    const float *x = nullptr, *W1 = nullptr, *b1 = nullptr,
                *W2 = nullptr, *b2 = nullptr, *ru = nullptr;
    for (int k = 0; k < n_in; k++) {
        switch (in_sizes[k]) {
            case 16777216: x  = (const float*)d_in[k]; break;
            case 6144:     W1 = (const float*)d_in[k]; break;
            case 128:      b1 = (const float*)d_in[k]; break;
            case 2048:     W2 = (const float*)d_in[k]; break;
            case 16:       b2 = (const float*)d_in[k]; break;
            case 1048576:  ru = (const float*)d_in[k]; break;
            default: break;
        }
    }
    float* out = (float*)d_out;

    cudaFuncSetAttribute(nca_pass1, cudaFuncAttributeMaxDynamicSharedMemorySize, SMEM_BYTES);
    nca_prep<<<24, 256>>>(W1, W2);
    nca_pass1<<<8192, 512, SMEM_BYTES>>>(x, b1, b2, ru, out);
    nca_pass2<<<4096, 256>>>(out);
    nca_probe<<<1, 32>>>();
}